// round 2
// baseline (speedup 1.0000x reference)
#include <cuda_runtime.h>
#include <cstdint>

// Problem constants (fixed shapes)
#define B_  4
#define T_  2048
#define D_  1024
#define H_  4
#define DK_ 256
#define DV_ 512
#define M_  (B_ * T_)        // 8192 rows
#define NKV (H_ * DK_)       // 1024
#define NV  (H_ * DV_)       // 2048

typedef unsigned long long ull;

// ---------------------------------------------------------------------------
// Scratch (device globals; no dynamic allocation allowed)
// ---------------------------------------------------------------------------
__device__ float g_normed[(size_t)M_ * D_];    // 32 MB
__device__ float g_q[(size_t)M_ * NKV];        // 32 MB
__device__ float g_k[(size_t)M_ * NKV];        // 32 MB
__device__ float g_v[(size_t)M_ * NV];         // 64 MB
__device__ float g_beta[(size_t)M_ * H_];      // 128 KB
__device__ float g_o[(size_t)M_ * NV];         // 64 MB (scan out, RMS-normed in place)

// ---------------------------------------------------------------------------
// f32x2 packed-FMA helpers (Blackwell FFMA2: 2 MACs / instruction)
// ---------------------------------------------------------------------------
__device__ __forceinline__ ull pack2(float x, float y) {
    ull r;
    asm("mov.b64 %0, {%1, %2};" : "=l"(r) : "f"(x), "f"(y));
    return r;
}
__device__ __forceinline__ void unpack2(ull v, float& x, float& y) {
    asm("mov.b64 {%0, %1}, %2;" : "=f"(x), "=f"(y) : "l"(v));
}
__device__ __forceinline__ void ffma2(ull& d, ull a, ull b) {
    asm("fma.rn.f32x2 %0, %1, %2, %0;" : "+l"(d) : "l"(a), "l"(b));
}

__device__ __forceinline__ float sigmoidf_(float x) {
    return 1.0f / (1.0f + __expf(-x));
}
__device__ __forceinline__ float siluf_(float x) {
    return x * sigmoidf_(x);
}

// ---------------------------------------------------------------------------
// 1) LayerNorm: x[8192,1024] -> g_normed
//    one block (256 thr) per row, float4 per thread
// ---------------------------------------------------------------------------
__global__ void __launch_bounds__(256) ln_kernel(const float* __restrict__ x,
                                                 const float* __restrict__ w,
                                                 const float* __restrict__ b) {
    const int row = blockIdx.x;
    const int tid = threadIdx.x;
    const float4 v = ((const float4*)(x + (size_t)row * D_))[tid];

    float s  = v.x + v.y + v.z + v.w;
    float s2 = v.x * v.x + v.y * v.y + v.z * v.z + v.w * v.w;

    #pragma unroll
    for (int off = 16; off > 0; off >>= 1) {
        s  += __shfl_xor_sync(0xffffffffu, s,  off);
        s2 += __shfl_xor_sync(0xffffffffu, s2, off);
    }
    __shared__ float sh[16];
    const int wid = tid >> 5, lane = tid & 31;
    if (lane == 0) { sh[wid] = s; sh[8 + wid] = s2; }
    __syncthreads();
    float ts = 0.f, ts2 = 0.f;
    #pragma unroll
    for (int i = 0; i < 8; ++i) { ts += sh[i]; ts2 += sh[8 + i]; }

    const float mean = ts * (1.0f / D_);
    const float var  = ts2 * (1.0f / D_) - mean * mean;
    const float rstd = rsqrtf(var + 1e-5f);

    const float4 wv = ((const float4*)w)[tid];
    const float4 bv = ((const float4*)b)[tid];
    float4 o;
    o.x = (v.x - mean) * rstd * wv.x + bv.x;
    o.y = (v.y - mean) * rstd * wv.y + bv.y;
    o.z = (v.z - mean) * rstd * wv.z + bv.z;
    o.w = (v.w - mean) * rstd * wv.w + bv.w;
    ((float4*)(g_normed + (size_t)row * D_))[tid] = o;
}

// ---------------------------------------------------------------------------
// 2) GEMM: C[M,N] = act(A[M,K] @ W[K,N]) (+ resid)
//    128x128x16 tile, 256 threads, 8x8 per thread, FFMA2 microkernel.
//    mode: 0 -> A=g_normed, C=g_q  (silu)
//          1 -> A=g_normed, C=g_k  (silu)
//          2 -> A=g_normed, C=g_v  (silu)
//          3 -> A=g_o,      C=Cext (none, + resid)
// ---------------------------------------------------------------------------
#define BM 128
#define BN 128
#define BK 16
#define BPAD 4

__global__ void __launch_bounds__(256, 1)
gemm_kernel(const float* __restrict__ W, float* __restrict__ Cext,
            const float* __restrict__ resid, int N, int K, int mode) {
    __shared__ float As[BK][BM + BPAD];
    __shared__ float Bs[BK][BN + BPAD];

    const float* A = (mode == 3) ? g_o : g_normed;
    float* C = (mode == 0) ? g_q : (mode == 1) ? g_k : (mode == 2) ? g_v : Cext;
    const bool do_silu = (mode < 3);

    const int tid = threadIdx.x;
    const int bm = blockIdx.y, bn = blockIdx.x;
    const int tm = tid >> 4, tn = tid & 15;   // 16x16 thread grid

    const float* Ab = A + (size_t)bm * BM * K;
    const float* Bb = W + (size_t)bn * BN;

    // A loads: idx = tid + 256*i -> row = idx/4, 4-col chunk = idx%4
    const int arow0 = tid >> 2;
    const int ac4   = tid & 3;
    // B loads: idx = tid + 256*i -> row = idx/32, col4 = (idx%32)*4
    const int brow0 = tid >> 5;
    const int bcol  = (tid & 31) * 4;

    ull acc[8][4];
    #pragma unroll
    for (int i = 0; i < 8; ++i)
        #pragma unroll
        for (int j = 0; j < 4; ++j) acc[i][j] = 0ull;

    const int KT = K / BK;
    float4 pa[2], pb[2];

    // prologue: load tile 0
    #pragma unroll
    for (int i = 0; i < 2; ++i) {
        pa[i] = *(const float4*)&Ab[(size_t)(arow0 + 64 * i) * K + ac4 * 4];
        pb[i] = *(const float4*)&Bb[(size_t)(brow0 + 8 * i) * N + bcol];
    }

    for (int kt = 0; kt < KT; ++kt) {
        __syncthreads();
        #pragma unroll
        for (int i = 0; i < 2; ++i) {
            const int r = arow0 + 64 * i;
            As[ac4 * 4 + 0][r] = pa[i].x;
            As[ac4 * 4 + 1][r] = pa[i].y;
            As[ac4 * 4 + 2][r] = pa[i].z;
            As[ac4 * 4 + 3][r] = pa[i].w;
            *(float4*)&Bs[brow0 + 8 * i][bcol] = pb[i];
        }
        __syncthreads();

        if (kt + 1 < KT) {
            const int k0 = (kt + 1) * BK;
            #pragma unroll
            for (int i = 0; i < 2; ++i) {
                pa[i] = *(const float4*)&Ab[(size_t)(arow0 + 64 * i) * K + k0 + ac4 * 4];
                pb[i] = *(const float4*)&Bb[(size_t)(k0 + brow0 + 8 * i) * N + bcol];
            }
        }

        #pragma unroll
        for (int kk = 0; kk < BK; ++kk) {
            const float4 a0 = *(const float4*)&As[kk][tm * 8];
            const float4 a1 = *(const float4*)&As[kk][tm * 8 + 4];
            ull a2[8];
            a2[0] = pack2(a0.x, a0.x); a2[1] = pack2(a0.y, a0.y);
            a2[2] = pack2(a0.z, a0.z); a2[3] = pack2(a0.w, a0.w);
            a2[4] = pack2(a1.x, a1.x); a2[5] = pack2(a1.y, a1.y);
            a2[6] = pack2(a1.z, a1.z); a2[7] = pack2(a1.w, a1.w);
            const ulonglong2 b01 = *(const ulonglong2*)&Bs[kk][tn * 8];
            const ulonglong2 b23 = *(const ulonglong2*)&Bs[kk][tn * 8 + 4];
            const ull bb0 = b01.x, bb1 = b01.y, bb2 = b23.x, bb3 = b23.y;
            #pragma unroll
            for (int i = 0; i < 8; ++i) {
                ffma2(acc[i][0], a2[i], bb0);
                ffma2(acc[i][1], a2[i], bb1);
                ffma2(acc[i][2], a2[i], bb2);
                ffma2(acc[i][3], a2[i], bb3);
            }
        }
    }

    // epilogue
    #pragma unroll
    for (int i = 0; i < 8; ++i) {
        float r[8];
        #pragma unroll
        for (int j = 0; j < 4; ++j) unpack2(acc[i][j], r[2 * j], r[2 * j + 1]);
        if (do_silu) {
            #pragma unroll
            for (int j = 0; j < 8; ++j) r[j] = siluf_(r[j]);
        }
        const size_t row = (size_t)bm * BM + tm * 8 + i;
        const size_t cb  = (size_t)bn * BN + tn * 8;
        if (resid != nullptr) {
            #pragma unroll
            for (int j = 0; j < 8; ++j) r[j] += resid[row * N + cb + j];
        }
        float4 w0 = make_float4(r[0], r[1], r[2], r[3]);
        float4 w1 = make_float4(r[4], r[5], r[6], r[7]);
        *(float4*)&C[row * N + cb]     = w0;
        *(float4*)&C[row * N + cb + 4] = w1;
    }
}

// ---------------------------------------------------------------------------
// 3) beta = sigmoid(normed @ Wb), Wb[1024,4]; one warp per row m
// ---------------------------------------------------------------------------
__global__ void __launch_bounds__(256) beta_kernel(const float* __restrict__ Wb) {
    const int warp = (blockIdx.x * blockDim.x + threadIdx.x) >> 5;
    const int lane = threadIdx.x & 31;
    if (warp >= M_) return;
    const float* nr = g_normed + (size_t)warp * D_;
    float a0 = 0, a1 = 0, a2 = 0, a3 = 0;
    for (int d = lane; d < D_; d += 32) {
        const float xn = nr[d];
        const float4 wv = *(const float4*)&Wb[d * 4];
        a0 += xn * wv.x; a1 += xn * wv.y; a2 += xn * wv.z; a3 += xn * wv.w;
    }
    #pragma unroll
    for (int off = 16; off > 0; off >>= 1) {
        a0 += __shfl_xor_sync(0xffffffffu, a0, off);
        a1 += __shfl_xor_sync(0xffffffffu, a1, off);
        a2 += __shfl_xor_sync(0xffffffffu, a2, off);
        a3 += __shfl_xor_sync(0xffffffffu, a3, off);
    }
    if (lane == 0) {
        float4 o = make_float4(sigmoidf_(a0), sigmoidf_(a1), sigmoidf_(a2), sigmoidf_(a3));
        *(float4*)&g_beta[(size_t)warp * 4] = o;
    }
}

// ---------------------------------------------------------------------------
// 4) l2norm over 256-element head groups of g_q (with *DK^-0.5) and g_k.
//    one warp per group (8 floats / lane); grid.y: 0 -> q, 1 -> k
// ---------------------------------------------------------------------------
__global__ void __launch_bounds__(256) l2norm_kernel() {
    const int grp  = blockIdx.x * 8 + (threadIdx.x >> 5);  // m*H + h
    const int lane = threadIdx.x & 31;
    float* base = ((blockIdx.y == 0) ? g_q : g_k) + (size_t)grp * DK_;
    float4 v0 = ((const float4*)base)[lane];
    float4 v1 = ((const float4*)base)[lane + 32];
    float ss = v0.x * v0.x + v0.y * v0.y + v0.z * v0.z + v0.w * v0.w
             + v1.x * v1.x + v1.y * v1.y + v1.z * v1.z + v1.w * v1.w;
    #pragma unroll
    for (int off = 16; off > 0; off >>= 1) ss += __shfl_xor_sync(0xffffffffu, ss, off);
    float sc = rsqrtf(ss + 1e-6f);
    if (blockIdx.y == 0) sc *= 0.0625f;  // DK^-0.5
    v0.x *= sc; v0.y *= sc; v0.z *= sc; v0.w *= sc;
    v1.x *= sc; v1.y *= sc; v1.z *= sc; v1.w *= sc;
    ((float4*)base)[lane]      = v0;
    ((float4*)base)[lane + 32] = v1;
}

// ---------------------------------------------------------------------------
// 5) Delta-rule scan. grid = B*H*8 = 128 CTAs, 256 threads.
//    CTA (b,h,c): dv chunk [c*64, c*64+64). Thread (g = tid&7, cp = tid>>3)
//    owns dk in [g*32, g*32+32), dv = {dv0+2cp, dv0+2cp+1} -> 64 state regs.
//    Reductions over dk across the 8-lane group via shfl_xor.
// ---------------------------------------------------------------------------
__global__ void __launch_bounds__(256, 1) scan_kernel() {
    const int blk = blockIdx.x;
    const int c = blk & 7;
    const int h = (blk >> 3) & 3;
    const int b = blk >> 5;
    const int dv0 = c * 64;
    const int tid = threadIdx.x;
    const int g  = tid & 7;
    const int cp = tid >> 3;

    __shared__ float ks[2][256], qs[2][256], vs[2][64], bs[2];

    float S0[32], S1[32];
    #pragma unroll
    for (int i = 0; i < 32; ++i) { S0[i] = 0.f; S1[i] = 0.f; }

    const size_t mbase = (size_t)b * T_;

    // preload t = 0
    {
        const size_t m = mbase;
        ks[0][tid] = g_k[m * NKV + h * DK_ + tid];
        qs[0][tid] = g_q[m * NKV + h * DK_ + tid];
        if (tid < 64) vs[0][tid] = g_v[m * NV + h * DV_ + dv0 + tid];
        if (tid == 0) bs[0] = g_beta[m * H_ + h];
    }
    __syncthreads();

    for (int t = 0; t < T_; ++t) {
        const int cur = t & 1, nxt = cur ^ 1;

        // prefetch step t+1 into registers (latency hidden under compute)
        float pk = 0.f, pq = 0.f, pv = 0.f, pb = 0.f;
        if (t + 1 < T_) {
            const size_t m = mbase + t + 1;
            pk = g_k[m * NKV + h * DK_ + tid];
            pq = g_q[m * NKV + h * DK_ + tid];
            if (tid < 64) pv = g_v[m * NV + h * DV_ + dv0 + tid];
            if (tid == 0) pb = g_beta[m * H_ + h];
        }

        float kr[32], qr[32];
        #pragma unroll
        for (int i = 0; i < 8; ++i) {
            const float4 t4 = *(const float4*)&ks[cur][g * 32 + i * 4];
            kr[4 * i] = t4.x; kr[4 * i + 1] = t4.y; kr[4 * i + 2] = t4.z; kr[4 * i + 3] = t4.w;
            const float4 u4 = *(const float4*)&qs[cur][g * 32 + i * 4];
            qr[4 * i] = u4.x; qr[4 * i + 1] = u4.y; qr[4 * i + 2] = u4.z; qr[4 * i + 3] = u4.w;
        }
        const float v0 = vs[cur][cp * 2], v1 = vs[cur][cp * 2 + 1];
        const float bt = bs[cur];

        // pred = k^T S_old (partial over this thread's dk, reduce over 8 lanes)
        float p0 = 0.f, p1 = 0.f;
        #pragma unroll
        for (int i = 0; i < 32; ++i) { p0 += kr[i] * S0[i]; p1 += kr[i] * S1[i]; }
        #pragma unroll
        for (int off = 1; off < 8; off <<= 1) {
            p0 += __shfl_xor_sync(0xffffffffu, p0, off);
            p1 += __shfl_xor_sync(0xffffffffu, p1, off);
        }
        const float vd0 = bt * (v0 - p0);
        const float vd1 = bt * (v1 - p1);

        // S_new = S_old + k vd^T ;  o = q^T S_new
        float o0 = 0.f, o1 = 0.f;
        #pragma unroll
        for (int i = 0; i < 32; ++i) {
            S0[i] += kr[i] * vd0;  o0 += qr[i] * S0[i];
            S1[i] += kr[i] * vd1;  o1 += qr[i] * S1[i];
        }
        #pragma unroll
        for (int off = 1; off < 8; off <<= 1) {
            o0 += __shfl_xor_sync(0xffffffffu, o0, off);
            o1 += __shfl_xor_sync(0xffffffffu, o1, off);
        }
        if (g == 0) {
            float2 st; st.x = o0; st.y = o1;
            *(float2*)&g_o[(mbase + t) * NV + h * DV_ + dv0 + cp * 2] = st;
        }

        // stage t+1
        ks[nxt][tid] = pk;
        qs[nxt][tid] = pq;
        if (tid < 64) vs[nxt][tid] = pv;
        if (tid == 0) bs[nxt] = pb;
        __syncthreads();
    }
}

// ---------------------------------------------------------------------------
// 6) per-head RMSNorm on g_o (in place): groups of 512, one warp per group
// ---------------------------------------------------------------------------
__global__ void __launch_bounds__(256) rmsnorm_kernel(const float* __restrict__ w) {
    const int grp  = blockIdx.x * 8 + (threadIdx.x >> 5);  // m*H + h
    const int lane = threadIdx.x & 31;
    float* base = g_o + (size_t)grp * DV_;
    float4 v[4];
    float ss = 0.f;
    #pragma unroll
    for (int i = 0; i < 4; ++i) {
        v[i] = ((const float4*)base)[lane + 32 * i];
        ss += v[i].x * v[i].x + v[i].y * v[i].y + v[i].z * v[i].z + v[i].w * v[i].w;
    }
    #pragma unroll
    for (int off = 16; off > 0; off >>= 1) ss += __shfl_xor_sync(0xffffffffu, ss, off);
    const float rs = rsqrtf(ss * (1.0f / DV_) + 1e-5f);
    #pragma unroll
    for (int i = 0; i < 4; ++i) {
        const int idx = lane + 32 * i;
        const float4 wv = ((const float4*)w)[idx];
        float4 o;
        o.x = v[i].x * rs * wv.x; o.y = v[i].y * rs * wv.y;
        o.z = v[i].z * rs * wv.z; o.w = v[i].w * rs * wv.w;
        ((float4*)base)[idx] = o;
    }
}

// ---------------------------------------------------------------------------
// Launch
// ---------------------------------------------------------------------------
extern "C" void kernel_launch(void* const* d_in, const int* in_sizes, int n_in,
                              void* d_out, int out_size) {
    const float* x        = (const float*)d_in[0];
    const float* ln_w     = (const float*)d_in[1];
    const float* ln_b     = (const float*)d_in[2];
    const float* Wq       = (const float*)d_in[3];
    const float* Wk       = (const float*)d_in[4];
    const float* Wv       = (const float*)d_in[5];
    const float* Wb       = (const float*)d_in[6];
    const float* o_norm_w = (const float*)d_in[7];
    const float* Wo       = (const float*)d_in[8];
    float* out = (float*)d_out;

    // 1) LayerNorm
    ln_kernel<<<M_, 256>>>(x, ln_w, ln_b);

    // 2) projections (silu fused into GEMM epilogue)
    gemm_kernel<<<dim3(NKV / BN, M_ / BM), 256>>>(Wq, nullptr, nullptr, NKV, D_, 0);
    gemm_kernel<<<dim3(NKV / BN, M_ / BM), 256>>>(Wk, nullptr, nullptr, NKV, D_, 1);
    gemm_kernel<<<dim3(NV  / BN, M_ / BM), 256>>>(Wv, nullptr, nullptr, NV,  D_, 2);

    // 3) beta
    beta_kernel<<<M_ / 8, 256>>>(Wb);

    // 4) l2norm on q (with DK^-0.5) and k
    l2norm_kernel<<<dim3((M_ * H_) / 8, 2), 256>>>();

    // 5) delta-rule scan
    scan_kernel<<<B_ * H_ * 8, 256>>>();

    // 6) per-head RMSNorm (in place on g_o)
    rmsnorm_kernel<<<(M_ * H_) / 8, 256>>>(o_norm_w);

    // 7) output projection + residual
    gemm_kernel<<<dim3(D_ / BN, M_ / BM), 256>>>(Wo, out, x, D_, NV, 3);
}

// round 4
// speedup vs baseline: 1.8577x; 1.8577x over previous
#include <cuda_runtime.h>
#include <cstdint>

// Problem constants (fixed shapes)
#define B_  4
#define T_  2048
#define D_  1024
#define H_  4
#define DK_ 256
#define DV_ 512
#define M_  (B_ * T_)        // 8192 rows
#define NKV (H_ * DK_)       // 1024
#define NV  (H_ * DV_)       // 2048
#define C_   64              // chunk length
#define NC_  32              // chunks per sequence
#define NCH  (B_ * H_ * NC_) // 512 chunk instances

typedef unsigned long long ull;

// ---------------------------------------------------------------------------
// Scratch (device globals; no dynamic allocation allowed)
// ---------------------------------------------------------------------------
__device__ float g_normed[(size_t)M_ * D_];
__device__ float g_q[(size_t)M_ * NKV];
__device__ float g_k[(size_t)M_ * NKV];
__device__ float g_v[(size_t)M_ * NV];
__device__ float g_beta[(size_t)M_ * H_];
__device__ float g_o[(size_t)M_ * NV];
// chunked-scan intermediates
__device__ float g_Wt [(size_t)NCH * DK_ * C_];  // [cIdx][kk][i]
__device__ float g_Qt [(size_t)NCH * DK_ * C_];  // [cIdx][kk][i]
__device__ float g_Pt [(size_t)NCH * C_ * C_];   // [cIdx][j][i]  (tril incl)
__device__ float g_mlt[(size_t)NCH * C_ * C_];   // [cIdx][i][j]  strict tril
__device__ float g_Uv [(size_t)NCH * C_ * DV_];  // [cIdx][i][dv]

// ---------------------------------------------------------------------------
// f32x2 packed-FMA helpers
// ---------------------------------------------------------------------------
__device__ __forceinline__ ull pack2(float x, float y) {
    ull r; asm("mov.b64 %0, {%1, %2};" : "=l"(r) : "f"(x), "f"(y)); return r;
}
__device__ __forceinline__ void unpack2(ull v, float& x, float& y) {
    asm("mov.b64 {%0, %1}, %2;" : "=f"(x), "=f"(y) : "l"(v));
}
__device__ __forceinline__ void ffma2(ull& d, ull a, ull b) {
    asm("fma.rn.f32x2 %0, %1, %2, %0;" : "+l"(d) : "l"(a), "l"(b));
}
// 4x4 micro-MMA: acc[r][0] covers cols (0,1), acc[r][1] covers (2,3)
__device__ __forceinline__ void mma4x4p(ull (&acc)[4][2], const float4 a4,
                                        const ull b0, const ull b1) {
    ull a;
    a = pack2(a4.x, a4.x); ffma2(acc[0][0], a, b0); ffma2(acc[0][1], a, b1);
    a = pack2(a4.y, a4.y); ffma2(acc[1][0], a, b0); ffma2(acc[1][1], a, b1);
    a = pack2(a4.z, a4.z); ffma2(acc[2][0], a, b0); ffma2(acc[2][1], a, b1);
    a = pack2(a4.w, a4.w); ffma2(acc[3][0], a, b0); ffma2(acc[3][1], a, b1);
}
__device__ __forceinline__ void unp4x4(const ull (&acc)[4][2], float (&o)[4][4]) {
    #pragma unroll
    for (int r = 0; r < 4; ++r) {
        unpack2(acc[r][0], o[r][0], o[r][1]);
        unpack2(acc[r][1], o[r][2], o[r][3]);
    }
}

__device__ __forceinline__ float sigmoidf_(float x) { return 1.0f / (1.0f + __expf(-x)); }
__device__ __forceinline__ float siluf_(float x)    { return x * sigmoidf_(x); }

// ---------------------------------------------------------------------------
// 1) LayerNorm
// ---------------------------------------------------------------------------
__global__ void __launch_bounds__(256) ln_kernel(const float* __restrict__ x,
                                                 const float* __restrict__ w,
                                                 const float* __restrict__ b) {
    const int row = blockIdx.x;
    const int tid = threadIdx.x;
    const float4 v = ((const float4*)(x + (size_t)row * D_))[tid];

    float s  = v.x + v.y + v.z + v.w;
    float s2 = v.x * v.x + v.y * v.y + v.z * v.z + v.w * v.w;
    #pragma unroll
    for (int off = 16; off > 0; off >>= 1) {
        s  += __shfl_xor_sync(0xffffffffu, s,  off);
        s2 += __shfl_xor_sync(0xffffffffu, s2, off);
    }
    __shared__ float sh[16];
    const int wid = tid >> 5, lane = tid & 31;
    if (lane == 0) { sh[wid] = s; sh[8 + wid] = s2; }
    __syncthreads();
    float ts = 0.f, ts2 = 0.f;
    #pragma unroll
    for (int i = 0; i < 8; ++i) { ts += sh[i]; ts2 += sh[8 + i]; }

    const float mean = ts * (1.0f / D_);
    const float var  = ts2 * (1.0f / D_) - mean * mean;
    const float rstd = rsqrtf(var + 1e-5f);

    const float4 wv = ((const float4*)w)[tid];
    const float4 bv = ((const float4*)b)[tid];
    float4 o;
    o.x = (v.x - mean) * rstd * wv.x + bv.x;
    o.y = (v.y - mean) * rstd * wv.y + bv.y;
    o.z = (v.z - mean) * rstd * wv.z + bv.z;
    o.w = (v.w - mean) * rstd * wv.w + bv.w;
    ((float4*)(g_normed + (size_t)row * D_))[tid] = o;
}

// ---------------------------------------------------------------------------
// 2) GEMM (unchanged from R1)
// ---------------------------------------------------------------------------
#define BM 128
#define BN 128
#define BK 16
#define BPAD 4

__global__ void __launch_bounds__(256, 1)
gemm_kernel(const float* __restrict__ W, float* __restrict__ Cext,
            const float* __restrict__ resid, int N, int K, int mode) {
    __shared__ float As[BK][BM + BPAD];
    __shared__ float Bs[BK][BN + BPAD];

    const float* A = (mode == 3) ? g_o : g_normed;
    float* C = (mode == 0) ? g_q : (mode == 1) ? g_k : (mode == 2) ? g_v : Cext;
    const bool do_silu = (mode < 3);

    const int tid = threadIdx.x;
    const int bm = blockIdx.y, bn = blockIdx.x;
    const int tm = tid >> 4, tn = tid & 15;

    const float* Ab = A + (size_t)bm * BM * K;
    const float* Bb = W + (size_t)bn * BN;

    const int arow0 = tid >> 2;
    const int ac4   = tid & 3;
    const int brow0 = tid >> 5;
    const int bcol  = (tid & 31) * 4;

    ull acc[8][4];
    #pragma unroll
    for (int i = 0; i < 8; ++i)
        #pragma unroll
        for (int j = 0; j < 4; ++j) acc[i][j] = 0ull;

    const int KT = K / BK;
    float4 pa[2], pb[2];

    #pragma unroll
    for (int i = 0; i < 2; ++i) {
        pa[i] = *(const float4*)&Ab[(size_t)(arow0 + 64 * i) * K + ac4 * 4];
        pb[i] = *(const float4*)&Bb[(size_t)(brow0 + 8 * i) * N + bcol];
    }

    for (int kt = 0; kt < KT; ++kt) {
        __syncthreads();
        #pragma unroll
        for (int i = 0; i < 2; ++i) {
            const int r = arow0 + 64 * i;
            As[ac4 * 4 + 0][r] = pa[i].x;
            As[ac4 * 4 + 1][r] = pa[i].y;
            As[ac4 * 4 + 2][r] = pa[i].z;
            As[ac4 * 4 + 3][r] = pa[i].w;
            *(float4*)&Bs[brow0 + 8 * i][bcol] = pb[i];
        }
        __syncthreads();

        if (kt + 1 < KT) {
            const int k0 = (kt + 1) * BK;
            #pragma unroll
            for (int i = 0; i < 2; ++i) {
                pa[i] = *(const float4*)&Ab[(size_t)(arow0 + 64 * i) * K + k0 + ac4 * 4];
                pb[i] = *(const float4*)&Bb[(size_t)(k0 + brow0 + 8 * i) * N + bcol];
            }
        }

        #pragma unroll
        for (int kk = 0; kk < BK; ++kk) {
            const float4 a0 = *(const float4*)&As[kk][tm * 8];
            const float4 a1 = *(const float4*)&As[kk][tm * 8 + 4];
            ull a2[8];
            a2[0] = pack2(a0.x, a0.x); a2[1] = pack2(a0.y, a0.y);
            a2[2] = pack2(a0.z, a0.z); a2[3] = pack2(a0.w, a0.w);
            a2[4] = pack2(a1.x, a1.x); a2[5] = pack2(a1.y, a1.y);
            a2[6] = pack2(a1.z, a1.z); a2[7] = pack2(a1.w, a1.w);
            const ulonglong2 b01 = *(const ulonglong2*)&Bs[kk][tn * 8];
            const ulonglong2 b23 = *(const ulonglong2*)&Bs[kk][tn * 8 + 4];
            const ull bb0 = b01.x, bb1 = b01.y, bb2 = b23.x, bb3 = b23.y;
            #pragma unroll
            for (int i = 0; i < 8; ++i) {
                ffma2(acc[i][0], a2[i], bb0);
                ffma2(acc[i][1], a2[i], bb1);
                ffma2(acc[i][2], a2[i], bb2);
                ffma2(acc[i][3], a2[i], bb3);
            }
        }
    }

    #pragma unroll
    for (int i = 0; i < 8; ++i) {
        float r[8];
        #pragma unroll
        for (int j = 0; j < 4; ++j) unpack2(acc[i][j], r[2 * j], r[2 * j + 1]);
        if (do_silu) {
            #pragma unroll
            for (int j = 0; j < 8; ++j) r[j] = siluf_(r[j]);
        }
        const size_t row = (size_t)bm * BM + tm * 8 + i;
        const size_t cb  = (size_t)bn * BN + tn * 8;
        if (resid != nullptr) {
            #pragma unroll
            for (int j = 0; j < 8; ++j) r[j] += resid[row * N + cb + j];
        }
        *(float4*)&C[row * N + cb]     = make_float4(r[0], r[1], r[2], r[3]);
        *(float4*)&C[row * N + cb + 4] = make_float4(r[4], r[5], r[6], r[7]);
    }
}

// ---------------------------------------------------------------------------
// 3) beta = sigmoid(normed @ Wb)
// ---------------------------------------------------------------------------
__global__ void __launch_bounds__(256) beta_kernel(const float* __restrict__ Wb) {
    const int warp = (blockIdx.x * blockDim.x + threadIdx.x) >> 5;
    const int lane = threadIdx.x & 31;
    if (warp >= M_) return;
    const float* nr = g_normed + (size_t)warp * D_;
    float a0 = 0, a1 = 0, a2 = 0, a3 = 0;
    for (int d = lane; d < D_; d += 32) {
        const float xn = nr[d];
        const float4 wv = *(const float4*)&Wb[d * 4];
        a0 += xn * wv.x; a1 += xn * wv.y; a2 += xn * wv.z; a3 += xn * wv.w;
    }
    #pragma unroll
    for (int off = 16; off > 0; off >>= 1) {
        a0 += __shfl_xor_sync(0xffffffffu, a0, off);
        a1 += __shfl_xor_sync(0xffffffffu, a1, off);
        a2 += __shfl_xor_sync(0xffffffffu, a2, off);
        a3 += __shfl_xor_sync(0xffffffffu, a3, off);
    }
    if (lane == 0) {
        *(float4*)&g_beta[(size_t)warp * 4] =
            make_float4(sigmoidf_(a0), sigmoidf_(a1), sigmoidf_(a2), sigmoidf_(a3));
    }
}

// ---------------------------------------------------------------------------
// 4) l2norm on q (with DK^-0.5) and k
// ---------------------------------------------------------------------------
__global__ void __launch_bounds__(256) l2norm_kernel() {
    const int grp  = blockIdx.x * 8 + (threadIdx.x >> 5);
    const int lane = threadIdx.x & 31;
    float* base = ((blockIdx.y == 0) ? g_q : g_k) + (size_t)grp * DK_;
    float4 v0 = ((const float4*)base)[lane];
    float4 v1 = ((const float4*)base)[lane + 32];
    float ss = v0.x * v0.x + v0.y * v0.y + v0.z * v0.z + v0.w * v0.w
             + v1.x * v1.x + v1.y * v1.y + v1.z * v1.z + v1.w * v1.w;
    #pragma unroll
    for (int off = 16; off > 0; off >>= 1) ss += __shfl_xor_sync(0xffffffffu, ss, off);
    float sc = rsqrtf(ss + 1e-6f);
    if (blockIdx.y == 0) sc *= 0.0625f;
    v0.x *= sc; v0.y *= sc; v0.z *= sc; v0.w *= sc;
    v1.x *= sc; v1.y *= sc; v1.z *= sc; v1.w *= sc;
    ((float4*)base)[lane]      = v0;
    ((float4*)base)[lane + 32] = v1;
}

// ---------------------------------------------------------------------------
// 5a) prep1: per chunk instance, compute
//     M  = strict_tril(beta_i * k_i.k_j)           -> g_mlt
//     W  = (I+M)^{-1} (beta K), stored transposed  -> g_Wt[kk][i]
//     Pt = transpose(tril_incl(Q K^T))             -> g_Pt[j][i]
//     Qt = Q transposed                            -> g_Qt[kk][i]
// smem floats: Kt[256*68] | U1[17408] (wb 64*260 / Qts 256*68) | Ms[64*68] | bsm[64]
// ---------------------------------------------------------------------------
#define P1_FLOATS (17408 + 17408 + 4352 + 64)
#define P1_BYTES  (P1_FLOATS * 4)

__global__ void __launch_bounds__(256, 1) prep1_kernel() {
    extern __shared__ float sm1[];
    float* Kt  = sm1;            // [256][68]
    float* wb  = sm1 + 17408;    // [64][260]
    float* Qts = sm1 + 17408;    // [256][68]  (aliases wb; wb dead by then)
    float* Ms  = sm1 + 34816;    // [64][68]
    float* bsm = sm1 + 39168;    // [64]

    const int tid  = threadIdx.x;
    const int cIdx = blockIdx.x;
    const int n = cIdx & 31, h = (cIdx >> 5) & 3, b = cIdx >> 7;
    const size_t m0 = (size_t)b * T_ + n * C_;
    const int hK = h * DK_;

    if (tid < 64) bsm[tid] = g_beta[(m0 + tid) * H_ + h];
    __syncthreads();

    // load K chunk: Kt (transposed) + wb (= beta_i * k_i, row layout)
    #pragma unroll 4
    for (int p = 0; p < 16; ++p) {
        const int idx = tid + p * 256;           // 0..4095 float4s
        const int i = idx >> 6, c4 = idx & 63;
        const float4 v = *(const float4*)&g_k[(m0 + i) * NKV + hK + c4 * 4];
        Kt[(c4 * 4 + 0) * 68 + i] = v.x;
        Kt[(c4 * 4 + 1) * 68 + i] = v.y;
        Kt[(c4 * 4 + 2) * 68 + i] = v.z;
        Kt[(c4 * 4 + 3) * 68 + i] = v.w;
        const float bb = bsm[i];
        *(float4*)&wb[i * 260 + c4 * 4] = make_float4(v.x * bb, v.y * bb, v.z * bb, v.w * bb);
    }
    __syncthreads();

    const int ty = tid >> 4, tx = tid & 15;
    const int ti4 = ty * 4, tj4 = tx * 4;

    // M = beta_i * strict_tril(K K^T)
    {
        ull acc[4][2] = {};
        #pragma unroll 4
        for (int kk = 0; kk < 256; ++kk) {
            const float4 a4 = *(const float4*)&Kt[kk * 68 + ti4];
            const float4 b4 = *(const float4*)&Kt[kk * 68 + tj4];
            mma4x4p(acc, a4, pack2(b4.x, b4.y), pack2(b4.z, b4.w));
        }
        float mo[4][4]; unp4x4(acc, mo);
        #pragma unroll
        for (int r = 0; r < 4; ++r) {
            const int i = ti4 + r;
            const float bi = bsm[i];
            #pragma unroll
            for (int cc = 0; cc < 4; ++cc) {
                const int j = tj4 + cc;
                Ms[i * 68 + j] = (j < i) ? bi * mo[r][cc] : 0.f;
            }
        }
    }
    __syncthreads();

    // forward substitution: W_i = beta_i k_i - sum_{j<i} M[i][j] W_j
    for (int i = 1; i < 64; ++i) {
        const float* mr = Ms + i * 68;
        float a0 = 0.f, a1 = 0.f, a2 = 0.f, a3 = 0.f;
        int j = 0;
        for (; j + 4 <= i; j += 4) {
            a0 += mr[j + 0] * wb[(j + 0) * 260 + tid];
            a1 += mr[j + 1] * wb[(j + 1) * 260 + tid];
            a2 += mr[j + 2] * wb[(j + 2) * 260 + tid];
            a3 += mr[j + 3] * wb[(j + 3) * 260 + tid];
        }
        for (; j < i; ++j) a0 += mr[j] * wb[j * 260 + tid];
        wb[i * 260 + tid] -= (a0 + a1) + (a2 + a3);
        __syncthreads();
    }

    // store Wt (transposed) + M
    {
        float* wt = g_Wt + (size_t)cIdx * (DK_ * C_);
        for (int idx = tid; idx < DK_ * C_; idx += 256) {
            const int kk = idx >> 6, i = idx & 63;
            wt[idx] = wb[i * 260 + kk];
        }
        float* mo = g_mlt + (size_t)cIdx * (C_ * C_);
        for (int idx = tid; idx < C_ * C_; idx += 256)
            mo[idx] = Ms[(idx >> 6) * 68 + (idx & 63)];
    }
    __syncthreads();   // wb dead; Qts may now overwrite

    // load Q chunk transposed into Qts
    #pragma unroll 4
    for (int p = 0; p < 16; ++p) {
        const int idx = tid + p * 256;
        const int i = idx >> 6, c4 = idx & 63;
        const float4 v = *(const float4*)&g_q[(m0 + i) * NKV + hK + c4 * 4];
        Qts[(c4 * 4 + 0) * 68 + i] = v.x;
        Qts[(c4 * 4 + 1) * 68 + i] = v.y;
        Qts[(c4 * 4 + 2) * 68 + i] = v.z;
        Qts[(c4 * 4 + 3) * 68 + i] = v.w;
    }
    __syncthreads();

    // Pt = transpose(tril_incl(Q K^T)) and Qt store
    {
        ull acc[4][2] = {};
        #pragma unroll 4
        for (int kk = 0; kk < 256; ++kk) {
            const float4 a4 = *(const float4*)&Qts[kk * 68 + ti4];
            const float4 b4 = *(const float4*)&Kt[kk * 68 + tj4];
            mma4x4p(acc, a4, pack2(b4.x, b4.y), pack2(b4.z, b4.w));
        }
        float po[4][4]; unp4x4(acc, po);
        float* pt = g_Pt + (size_t)cIdx * (C_ * C_);
        #pragma unroll
        for (int cc = 0; cc < 4; ++cc) {
            const int j = tj4 + cc;
            float4 v;
            v.x = (j <= ti4 + 0) ? po[0][cc] : 0.f;
            v.y = (j <= ti4 + 1) ? po[1][cc] : 0.f;
            v.z = (j <= ti4 + 2) ? po[2][cc] : 0.f;
            v.w = (j <= ti4 + 3) ? po[3][cc] : 0.f;
            *(float4*)&pt[j * 64 + ti4] = v;
        }
        float* qt = g_Qt + (size_t)cIdx * (DK_ * C_);
        for (int idx = tid; idx < DK_ * C_; idx += 256)
            qt[idx] = Qts[(idx >> 6) * 68 + (idx & 63)];
    }
}

// ---------------------------------------------------------------------------
// 5b) prep2: Uv = (I+M)^{-1} (beta V)  -> g_Uv
// smem floats: vb[64*520] | Ms[64*68] | bsm[64]
// ---------------------------------------------------------------------------
#define P2_FLOATS (33280 + 4352 + 64)
#define P2_BYTES  (P2_FLOATS * 4)

__global__ void __launch_bounds__(256, 1) prep2_kernel() {
    extern __shared__ float sm2[];
    float* vb  = sm2;            // [64][520]
    float* Ms  = sm2 + 33280;    // [64][68]
    float* bsm = sm2 + 33280 + 4352;

    const int tid  = threadIdx.x;
    const int cIdx = blockIdx.x;
    const int n = cIdx & 31, h = (cIdx >> 5) & 3, b = cIdx >> 7;
    const size_t m0 = (size_t)b * T_ + n * C_;
    const int hV = h * DV_;

    if (tid < 64) bsm[tid] = g_beta[(m0 + tid) * H_ + h];
    {
        const float* mg = g_mlt + (size_t)cIdx * (C_ * C_);
        for (int idx = tid; idx < C_ * C_; idx += 256)
            Ms[(idx >> 6) * 68 + (idx & 63)] = mg[idx];
    }
    __syncthreads();

    // load V chunk (x beta)
    #pragma unroll 4
    for (int p = 0; p < 32; ++p) {
        const int idx = tid + p * 256;           // 0..8191 float4s
        const int i = idx >> 7, c4 = idx & 127;
        float4 v = *(const float4*)&g_v[(m0 + i) * NV + hV + c4 * 4];
        const float bb = bsm[i];
        v.x *= bb; v.y *= bb; v.z *= bb; v.w *= bb;
        *(float4*)&vb[i * 520 + c4 * 4] = v;
    }
    __syncthreads();

    // forward substitution, 2 columns per thread (packed)
    const int col2 = 2 * tid;
    for (int i = 1; i < 64; ++i) {
        const float* mr = Ms + i * 68;
        ull acc = 0ull;
        for (int j = 0; j < i; ++j) {
            const float m = mr[j];
            const ull v = *(const ull*)&vb[j * 520 + col2];
            ffma2(acc, pack2(m, m), v);
        }
        float ax, ay; unpack2(acc, ax, ay);
        vb[i * 520 + col2]     -= ax;
        vb[i * 520 + col2 + 1] -= ay;
        __syncthreads();
    }

    // store
    float* uo = g_Uv + (size_t)cIdx * (C_ * DV_);
    #pragma unroll 4
    for (int p = 0; p < 32; ++p) {
        const int idx = tid + p * 256;
        const int i = idx >> 7, c4 = idx & 127;
        *(float4*)&uo[i * DV_ + c4 * 4] = *(const float4*)&vb[i * 520 + c4 * 4];
    }
}

// ---------------------------------------------------------------------------
// 5c) chunkscan: 128 CTAs = (b,h,dv-slice of 64). Per chunk n (sequential):
//     U = Uv - W S ; O = Q S + Pt^T U ; S += K^T U
// smem floats: S[16384] Ub[4096] Pts[4096] Uvs[4096] stW[2][4096] stQ[2][4096]
// ---------------------------------------------------------------------------
#define CS_FLOATS (16384 + 4096 * 3 + 4096 * 4)
#define CS_BYTES  (CS_FLOATS * 4)

__global__ void __launch_bounds__(256, 1) chunkscan_kernel() {
    extern __shared__ float sm3[];
    float* S   = sm3;                 // [256][64], dk-major
    float* Ub  = sm3 + 16384;         // [64][64]
    float* Pts = sm3 + 20480;         // [64][64]  Pt[j][i]
    float* Uvs = sm3 + 24576;         // [64][64]
    float* stWb[2] = { sm3 + 28672, sm3 + 32768 };
    float* stQb[2] = { sm3 + 36864, sm3 + 40960 };

    const int tid = threadIdx.x;
    const int c = blockIdx.x & 7, h = (blockIdx.x >> 3) & 3, b = blockIdx.x >> 5;
    const int dv0 = c * 64;
    const int ty = tid >> 4, tx = tid & 15;
    const int ti4 = ty * 4, tj4 = tx * 4;
    const int hK = h * DK_;

    for (int i = tid; i < 16384; i += 256) S[i] = 0.f;

    for (int n = 0; n < NC_; ++n) {
        const int cIdx = b * 128 + h * 32 + n;
        const float* Wt  = g_Wt + (size_t)cIdx * 16384;
        const float* Qt  = g_Qt + (size_t)cIdx * 16384;
        const float* Ptg = g_Pt + (size_t)cIdx * 4096;
        const float* Uvg = g_Uv + (size_t)cIdx * 32768 + dv0;
        const size_t m0  = (size_t)b * T_ + n * 64;

        // prefill Pts, Uvs, stW[0], stQ[0]
        #pragma unroll
        for (int p = 0; p < 4; ++p) {
            const int idx = tid + p * 256;          // float4 index 0..1023
            ((float4*)Pts)[idx] = ((const float4*)Ptg)[idx];
            const int r = idx >> 4, c4 = idx & 15;
            ((float4*)Uvs)[idx] = *(const float4*)&Uvg[r * DV_ + c4 * 4];
            ((float4*)stWb[0])[idx] = ((const float4*)Wt)[idx];
            ((float4*)stQb[0])[idx] = ((const float4*)Qt)[idx];
        }
        __syncthreads();

        // dual GEMM over 4 kk-blocks: aU += W*S, aO += Q*S
        ull aU[4][2] = {}, aO[4][2] = {};
        int cur = 0;
        for (int kb = 0; kb < 4; ++kb) {
            float4 rw[4], rq[4];
            if (kb < 3) {
                const float4* wsrc = (const float4*)(Wt + (kb + 1) * 4096);
                const float4* qsrc = (const float4*)(Qt + (kb + 1) * 4096);
                #pragma unroll
                for (int p = 0; p < 4; ++p) {
                    rw[p] = wsrc[tid + p * 256];
                    rq[p] = qsrc[tid + p * 256];
                }
            }
            const float* sw = stWb[cur];
            const float* sq = stQb[cur];
            const float* sb = S + kb * 4096;
            #pragma unroll 4
            for (int kk = 0; kk < 64; ++kk) {
                const float4 s4 = *(const float4*)&sb[kk * 64 + tj4];
                const ull b0 = pack2(s4.x, s4.y), b1 = pack2(s4.z, s4.w);
                mma4x4p(aU, *(const float4*)&sw[kk * 64 + ti4], b0, b1);
                mma4x4p(aO, *(const float4*)&sq[kk * 64 + ti4], b0, b1);
            }
            if (kb < 3) {
                #pragma unroll
                for (int p = 0; p < 4; ++p) {
                    ((float4*)stWb[cur ^ 1])[tid + p * 256] = rw[p];
                    ((float4*)stQb[cur ^ 1])[tid + p * 256] = rq[p];
                }
                cur ^= 1;
            }
            __syncthreads();
        }

        // finalize U = Uv - aU; write to Ub. Also prefetch K block 0.
        {
            float su[4][4]; unp4x4(aU, su);
            #pragma unroll
            for (int r = 0; r < 4; ++r) {
                const float4 uv = *(const float4*)&Uvs[(ti4 + r) * 64 + tj4];
                *(float4*)&Ub[(ti4 + r) * 64 + tj4] =
                    make_float4(uv.x - su[r][0], uv.y - su[r][1],
                                uv.z - su[r][2], uv.w - su[r][3]);
            }
        }
        float4 rk[4];
        #pragma unroll
        for (int p = 0; p < 4; ++p) {
            const int idx = tid + p * 256;
            const int i = idx >> 4, d4 = idx & 15;
            rk[p] = *(const float4*)&g_k[(m0 + i) * NKV + hK + d4 * 4];
        }
        #pragma unroll
        for (int p = 0; p < 4; ++p) ((float4*)stWb[0])[tid + p * 256] = rk[p];
        __syncthreads();

        // O += Pt^T U  (aO[r][*] for row i = ti4+r)
        #pragma unroll 4
        for (int j = 0; j < 64; ++j) {
            const float4 u4 = *(const float4*)&Ub[j * 64 + tj4];
            mma4x4p(aO, *(const float4*)&Pts[j * 64 + ti4],
                    pack2(u4.x, u4.y), pack2(u4.z, u4.w));
        }
        {
            float oo[4][4]; unp4x4(aO, oo);
            #pragma unroll
            for (int r = 0; r < 4; ++r)
                *(float4*)&g_o[(m0 + ti4 + r) * NV + h * DV_ + dv0 + tj4] =
                    make_float4(oo[r][0], oo[r][1], oo[r][2], oo[r][3]);
        }

        // S += K^T U over 4 dk-blocks (stage K in stWb buffers)
        int cur2 = 0;
        for (int db = 0; db < 4; ++db) {
            float4 rk2[4];
            if (db < 3) {
                #pragma unroll
                for (int p = 0; p < 4; ++p) {
                    const int idx = tid + p * 256;
                    const int i = idx >> 4, d4 = idx & 15;
                    rk2[p] = *(const float4*)&g_k[(m0 + i) * NKV + hK + (db + 1) * 64 + d4 * 4];
                }
            }
            float* Sb = S + db * 4096;
            ull aS[4][2];
            #pragma unroll
            for (int r = 0; r < 4; ++r) {
                const float4 s4 = *(const float4*)&Sb[(ti4 + r) * 64 + tj4];
                aS[r][0] = pack2(s4.x, s4.y);
                aS[r][1] = pack2(s4.z, s4.w);
            }
            const float* sk = stWb[cur2];
            #pragma unroll 4
            for (int i2 = 0; i2 < 64; ++i2) {
                const float4 u4 = *(const float4*)&Ub[i2 * 64 + tj4];
                mma4x4p(aS, *(const float4*)&sk[i2 * 64 + ti4],
                        pack2(u4.x, u4.y), pack2(u4.z, u4.w));
            }
            {
                float so[4][4]; unp4x4(aS, so);
                #pragma unroll
                for (int r = 0; r < 4; ++r)
                    *(float4*)&Sb[(ti4 + r) * 64 + tj4] =
                        make_float4(so[r][0], so[r][1], so[r][2], so[r][3]);
            }
            if (db < 3) {
                #pragma unroll
                for (int p = 0; p < 4; ++p)
                    ((float4*)stWb[cur2 ^ 1])[tid + p * 256] = rk2[p];
                cur2 ^= 1;
            }
            __syncthreads();
        }
    }
}

// ---------------------------------------------------------------------------
// 6) per-head RMSNorm on g_o (in place)
// ---------------------------------------------------------------------------
__global__ void __launch_bounds__(256) rmsnorm_kernel(const float* __restrict__ w) {
    const int grp  = blockIdx.x * 8 + (threadIdx.x >> 5);
    const int lane = threadIdx.x & 31;
    float* base = g_o + (size_t)grp * DV_;
    float4 v[4];
    float ss = 0.f;
    #pragma unroll
    for (int i = 0; i < 4; ++i) {
        v[i] = ((const float4*)base)[lane + 32 * i];
        ss += v[i].x * v[i].x + v[i].y * v[i].y + v[i].z * v[i].z + v[i].w * v[i].w;
    }
    #pragma unroll
    for (int off = 16; off > 0; off >>= 1) ss += __shfl_xor_sync(0xffffffffu, ss, off);
    const float rs = rsqrtf(ss * (1.0f / DV_) + 1e-5f);
    #pragma unroll
    for (int i = 0; i < 4; ++i) {
        const int idx = lane + 32 * i;
        const float4 wv = ((const float4*)w)[idx];
        ((float4*)base)[idx] = make_float4(v[i].x * rs * wv.x, v[i].y * rs * wv.y,
                                           v[i].z * rs * wv.z, v[i].w * rs * wv.w);
    }
}

// ---------------------------------------------------------------------------
// Launch
// ---------------------------------------------------------------------------
extern "C" void kernel_launch(void* const* d_in, const int* in_sizes, int n_in,
                              void* d_out, int out_size) {
    const float* x        = (const float*)d_in[0];
    const float* ln_w     = (const float*)d_in[1];
    const float* ln_b     = (const float*)d_in[2];
    const float* Wq       = (const float*)d_in[3];
    const float* Wk       = (const float*)d_in[4];
    const float* Wv       = (const float*)d_in[5];
    const float* Wb       = (const float*)d_in[6];
    const float* o_norm_w = (const float*)d_in[7];
    const float* Wo       = (const float*)d_in[8];
    float* out = (float*)d_out;

    cudaFuncSetAttribute(prep1_kernel, cudaFuncAttributeMaxDynamicSharedMemorySize, P1_BYTES);
    cudaFuncSetAttribute(prep2_kernel, cudaFuncAttributeMaxDynamicSharedMemorySize, P2_BYTES);
    cudaFuncSetAttribute(chunkscan_kernel, cudaFuncAttributeMaxDynamicSharedMemorySize, CS_BYTES);

    ln_kernel<<<M_, 256>>>(x, ln_w, ln_b);

    gemm_kernel<<<dim3(NKV / BN, M_ / BM), 256>>>(Wq, nullptr, nullptr, NKV, D_, 0);
    gemm_kernel<<<dim3(NKV / BN, M_ / BM), 256>>>(Wk, nullptr, nullptr, NKV, D_, 1);
    gemm_kernel<<<dim3(NV  / BN, M_ / BM), 256>>>(Wv, nullptr, nullptr, NV,  D_, 2);

    beta_kernel<<<M_ / 8, 256>>>(Wb);
    l2norm_kernel<<<dim3((M_ * H_) / 8, 2), 256>>>();

    prep1_kernel<<<NCH, 256, P1_BYTES>>>();
    prep2_kernel<<<NCH, 256, P2_BYTES>>>();
    chunkscan_kernel<<<B_ * H_ * 8, 256, CS_BYTES>>>();

    rmsnorm_kernel<<<(M_ * H_) / 8, 256>>>(o_norm_w);

    gemm_kernel<<<dim3(D_ / BN, M_ / BM), 256>>>(Wo, out, x, D_, NV, 3);
}

// round 6
// speedup vs baseline: 3.5816x; 1.9279x over previous
#include <cuda_runtime.h>
#include <cuda_bf16.h>
#include <cstdint>

// Problem constants (fixed shapes)
#define B_  4
#define T_  2048
#define D_  1024
#define H_  4
#define DK_ 256
#define DV_ 512
#define M_  (B_ * T_)        // 8192 rows
#define NKV (H_ * DK_)       // 1024
#define NV  (H_ * DV_)       // 2048
#define C_   64              // chunk length
#define NC_  32              // chunks per sequence
#define NCH  (B_ * H_ * NC_) // 512 chunk instances

typedef unsigned long long ull;

// ---------------------------------------------------------------------------
// Scratch (device globals; no dynamic allocation allowed)
// ---------------------------------------------------------------------------
__device__ float g_normed[(size_t)M_ * D_];
__device__ float g_q[(size_t)M_ * NKV];
__device__ float g_k[(size_t)M_ * NKV];
__device__ float g_v[(size_t)M_ * NV];
__device__ float g_beta[(size_t)M_ * H_];
__device__ float g_o[(size_t)M_ * NV];
// chunked-scan intermediates
__device__ float g_Wt [(size_t)NCH * DK_ * C_];  // [cIdx][kk][i]
__device__ float g_Qt [(size_t)NCH * DK_ * C_];  // [cIdx][kk][i]
__device__ float g_Pt [(size_t)NCH * C_ * C_];   // [cIdx][j][i]  (tril incl)
__device__ float g_mlt[(size_t)NCH * C_ * C_];   // [cIdx][i][j]  strict tril
__device__ float g_Uv [(size_t)NCH * C_ * DV_];  // [cIdx][i][dv]
// bf16 split operands for tensor-core GEMMs
__device__ __nv_bfloat16 g_nh[(size_t)M_ * D_];
__device__ __nv_bfloat16 g_nl[(size_t)M_ * D_];
__device__ __nv_bfloat16 g_oh[(size_t)M_ * NV];
__device__ __nv_bfloat16 g_ol[(size_t)M_ * NV];
__device__ __nv_bfloat16 g_Wqt_h[(size_t)NKV * D_];
__device__ __nv_bfloat16 g_Wqt_l[(size_t)NKV * D_];
__device__ __nv_bfloat16 g_Wkt_h[(size_t)NKV * D_];
__device__ __nv_bfloat16 g_Wkt_l[(size_t)NKV * D_];
__device__ __nv_bfloat16 g_Wvt_h[(size_t)NV * D_];
__device__ __nv_bfloat16 g_Wvt_l[(size_t)NV * D_];
__device__ __nv_bfloat16 g_Wot_h[(size_t)D_ * NV];
__device__ __nv_bfloat16 g_Wot_l[(size_t)D_ * NV];

// ---------------------------------------------------------------------------
// f32x2 packed-FMA helpers
// ---------------------------------------------------------------------------
__device__ __forceinline__ ull pack2(float x, float y) {
    ull r; asm("mov.b64 %0, {%1, %2};" : "=l"(r) : "f"(x), "f"(y)); return r;
}
__device__ __forceinline__ void unpack2(ull v, float& x, float& y) {
    asm("mov.b64 {%0, %1}, %2;" : "=f"(x), "=f"(y) : "l"(v));
}
__device__ __forceinline__ void ffma2(ull& d, ull a, ull b) {
    asm("fma.rn.f32x2 %0, %1, %2, %0;" : "+l"(d) : "l"(a), "l"(b));
}
__device__ __forceinline__ void mma4x4p(ull (&acc)[4][2], const float4 a4,
                                        const ull b0, const ull b1) {
    ull a;
    a = pack2(a4.x, a4.x); ffma2(acc[0][0], a, b0); ffma2(acc[0][1], a, b1);
    a = pack2(a4.y, a4.y); ffma2(acc[1][0], a, b0); ffma2(acc[1][1], a, b1);
    a = pack2(a4.z, a4.z); ffma2(acc[2][0], a, b0); ffma2(acc[2][1], a, b1);
    a = pack2(a4.w, a4.w); ffma2(acc[3][0], a, b0); ffma2(acc[3][1], a, b1);
}
__device__ __forceinline__ void unp4x4(const ull (&acc)[4][2], float (&o)[4][4]) {
    #pragma unroll
    for (int r = 0; r < 4; ++r) {
        unpack2(acc[r][0], o[r][0], o[r][1]);
        unpack2(acc[r][1], o[r][2], o[r][3]);
    }
}

__device__ __forceinline__ float sigmoidf_(float x) { return 1.0f / (1.0f + __expf(-x)); }
__device__ __forceinline__ float siluf_(float x)    { return x * sigmoidf_(x); }

// split fp32 -> (hi, lo) bf16 pair; store 4 at idx (idx multiple of 4)
__device__ __forceinline__ void split_store4(const float4 v,
                                             __nv_bfloat16* __restrict__ hp,
                                             __nv_bfloat16* __restrict__ lp,
                                             size_t idx) {
    __nv_bfloat16 hx = __float2bfloat16(v.x), hy = __float2bfloat16(v.y);
    __nv_bfloat16 hz = __float2bfloat16(v.z), hw = __float2bfloat16(v.w);
    __nv_bfloat16 lx = __float2bfloat16(v.x - __bfloat162float(hx));
    __nv_bfloat16 ly = __float2bfloat16(v.y - __bfloat162float(hy));
    __nv_bfloat16 lz = __float2bfloat16(v.z - __bfloat162float(hz));
    __nv_bfloat16 lw = __float2bfloat16(v.w - __bfloat162float(hw));
    __nv_bfloat162 t;
    t.x = hx; t.y = hy; *(__nv_bfloat162*)(hp + idx)     = t;
    t.x = hz; t.y = hw; *(__nv_bfloat162*)(hp + idx + 2) = t;
    t.x = lx; t.y = ly; *(__nv_bfloat162*)(lp + idx)     = t;
    t.x = lz; t.y = lw; *(__nv_bfloat162*)(lp + idx + 2) = t;
}

// ---------------------------------------------------------------------------
// mma.sync helpers (arch-portable HMMA; works on plain sm_100 target)
// ---------------------------------------------------------------------------
__device__ __forceinline__ uint32_t smem_u32(const void* p) {
    uint32_t a;
    asm("{ .reg .u64 t; cvta.to.shared.u64 t, %1; cvt.u32.u64 %0, t; }" : "=r"(a) : "l"(p));
    return a;
}
__device__ __forceinline__ void ldsm4(uint32_t* r, uint32_t addr) {
    asm volatile("ldmatrix.sync.aligned.m8n8.x4.shared.b16 {%0,%1,%2,%3}, [%4];"
        : "=r"(r[0]), "=r"(r[1]), "=r"(r[2]), "=r"(r[3]) : "r"(addr));
}
__device__ __forceinline__ void mma16816(float* c, const uint32_t* a, const uint32_t* b) {
    asm volatile(
        "mma.sync.aligned.m16n8k16.row.col.f32.bf16.bf16.f32 "
        "{%0,%1,%2,%3}, {%4,%5,%6,%7}, {%8,%9}, {%0,%1,%2,%3};"
        : "+f"(c[0]), "+f"(c[1]), "+f"(c[2]), "+f"(c[3])
        : "r"(a[0]), "r"(a[1]), "r"(a[2]), "r"(a[3]), "r"(b[0]), "r"(b[1]));
}

// ---------------------------------------------------------------------------
// 1) LayerNorm -> g_normed (fp32) + g_nh/g_nl (bf16 split)
// ---------------------------------------------------------------------------
__global__ void __launch_bounds__(256) ln_kernel(const float* __restrict__ x,
                                                 const float* __restrict__ w,
                                                 const float* __restrict__ b) {
    const int row = blockIdx.x;
    const int tid = threadIdx.x;
    const float4 v = ((const float4*)(x + (size_t)row * D_))[tid];

    float s  = v.x + v.y + v.z + v.w;
    float s2 = v.x * v.x + v.y * v.y + v.z * v.z + v.w * v.w;
    #pragma unroll
    for (int off = 16; off > 0; off >>= 1) {
        s  += __shfl_xor_sync(0xffffffffu, s,  off);
        s2 += __shfl_xor_sync(0xffffffffu, s2, off);
    }
    __shared__ float sh[16];
    const int wid = tid >> 5, lane = tid & 31;
    if (lane == 0) { sh[wid] = s; sh[8 + wid] = s2; }
    __syncthreads();
    float ts = 0.f, ts2 = 0.f;
    #pragma unroll
    for (int i = 0; i < 8; ++i) { ts += sh[i]; ts2 += sh[8 + i]; }

    const float mean = ts * (1.0f / D_);
    const float var  = ts2 * (1.0f / D_) - mean * mean;
    const float rstd = rsqrtf(var + 1e-5f);

    const float4 wv = ((const float4*)w)[tid];
    const float4 bv = ((const float4*)b)[tid];
    float4 o;
    o.x = (v.x - mean) * rstd * wv.x + bv.x;
    o.y = (v.y - mean) * rstd * wv.y + bv.y;
    o.z = (v.z - mean) * rstd * wv.z + bv.z;
    o.w = (v.w - mean) * rstd * wv.w + bv.w;
    const size_t base = (size_t)row * D_;
    ((float4*)(g_normed + base))[tid] = o;
    split_store4(o, g_nh, g_nl, base + (size_t)tid * 4);
}

// ---------------------------------------------------------------------------
// 1b) weight transpose + bf16 split: W[K][N] fp32 -> T_hi/T_lo [N][K] bf16
// ---------------------------------------------------------------------------
__global__ void __launch_bounds__(256) wtrans_kernel(const float* __restrict__ W,
                                                     __nv_bfloat16* __restrict__ Th,
                                                     __nv_bfloat16* __restrict__ Tl,
                                                     int K, int N) {
    __shared__ float tile[32][33];
    const int tx = threadIdx.x & 31, ty = threadIdx.x >> 5;  // ty 0..7
    const int k0 = blockIdx.y * 32, n0 = blockIdx.x * 32;
    #pragma unroll
    for (int i = 0; i < 32; i += 8)
        tile[ty + i][tx] = W[(size_t)(k0 + ty + i) * N + n0 + tx];
    __syncthreads();
    #pragma unroll
    for (int i = 0; i < 32; i += 8) {
        const float v = tile[tx][ty + i];
        const size_t oi = (size_t)(n0 + ty + i) * K + k0 + tx;
        const __nv_bfloat16 h = __float2bfloat16(v);
        Th[oi] = h;
        Tl[oi] = __float2bfloat16(v - __bfloat162float(h));
    }
}

// ---------------------------------------------------------------------------
// 2) HMMA GEMM: C[M,N] = act(A[M,K] @ Bt[N,K]^T) (+resid)
//    split-bf16: Ah*Bh + Ah*Bl + Al*Bh, fp32 accum.
//    128x128 CTA tile, 8 warps (2x4), 64x32 per warp, k-block 64,
//    double-buffered SMEM (2 x 64KB), XOR-swizzled for conflict-free ldmatrix.
// ---------------------------------------------------------------------------
#define MG_STAGE 65536
#define MG_SMEM  (2 * MG_STAGE)

__global__ void __launch_bounds__(256, 1)
mma_gemm(const __nv_bfloat16* __restrict__ Ah, const __nv_bfloat16* __restrict__ Al,
         const __nv_bfloat16* __restrict__ Bh, const __nv_bfloat16* __restrict__ Bl,
         float* __restrict__ C, const float* __restrict__ resid,
         int N, int K, int do_silu) {
    extern __shared__ char smx[];
    const uint32_t sbase = smem_u32(smx);
    const int tid = threadIdx.x;
    const int lane = tid & 31;
    const int wid = tid >> 5;
    const int wm = wid >> 2;          // 0..1 -> m offset 64*wm
    const int wn = wid & 3;           // 0..3 -> n offset 32*wn
    const int m0w = wm * 64, n0w = wn * 32;

    const size_t bm = (size_t)blockIdx.y * 128;
    const size_t bn = (size_t)blockIdx.x * 128;
    const __nv_bfloat16* pAh = Ah + bm * K;
    const __nv_bfloat16* pAl = Al + bm * K;
    const __nv_bfloat16* pBh = Bh + bn * K;
    const __nv_bfloat16* pBl = Bl + bn * K;

    // loader mapping: idx = tid + p*256 over 1024 -> row 0..127, 16B chunk 0..7
    // smem tile offset: row*128 + ((ch ^ (row&7)) << 4); tiles: Ah 0, Al 16K, Bh 32K, Bl 48K
    // prologue: stage 0 (k0 = 0)
    {
        char* stg = smx;
        #pragma unroll
        for (int p = 0; p < 4; ++p) {
            const int c = tid + (p << 8);
            const int row = c >> 3, ch = c & 7;
            const size_t gi = (size_t)row * K + (ch << 3);
            const int off = (row << 7) + (((ch ^ (row & 7))) << 4);
            *(uint4*)(stg + off)         = *(const uint4*)(pAh + gi);
            *(uint4*)(stg + 16384 + off) = *(const uint4*)(pAl + gi);
            *(uint4*)(stg + 32768 + off) = *(const uint4*)(pBh + gi);
            *(uint4*)(stg + 49152 + off) = *(const uint4*)(pBl + gi);
        }
    }
    __syncthreads();

    float acc[4][4][4];
    #pragma unroll
    for (int i = 0; i < 4; ++i)
        #pragma unroll
        for (int j = 0; j < 4; ++j)
            #pragma unroll
            for (int q = 0; q < 4; ++q) acc[i][j][q] = 0.f;

    // precomputed ldmatrix lane roles
    const int a_row = m0w + (lane & 15);          // + mt*16
    const int a_chs = lane >> 4;                  // 0/1 within k16
    const int b_row = n0w + ((lane >> 3) & 2) * 4 + (lane & 7);  // + npair*16
    const int b_chs = (lane >> 3) & 1;

    const int KB = K >> 6;
    for (int kb = 0; kb < KB; ++kb) {
        const uint32_t stg = sbase + (uint32_t)(kb & 1) * MG_STAGE;
        const bool hasNext = (kb + 1) < KB;

        uint4 vAh[4], vAl[4], vBh[4], vBl[4];
        if (hasNext) {
            const int k0 = (kb + 1) << 6;
            #pragma unroll
            for (int p = 0; p < 4; ++p) {
                const int c = tid + (p << 8);
                const int row = c >> 3, ch = c & 7;
                const size_t gi = (size_t)row * K + k0 + (ch << 3);
                vAh[p] = *(const uint4*)(pAh + gi);
                vAl[p] = *(const uint4*)(pAl + gi);
                vBh[p] = *(const uint4*)(pBh + gi);
                vBl[p] = *(const uint4*)(pBl + gi);
            }
        }

        #pragma unroll
        for (int ks = 0; ks < 4; ++ks) {
            uint32_t afh[4][4], afl[4][4];
            #pragma unroll
            for (int mt = 0; mt < 4; ++mt) {
                const int row = a_row + mt * 16;
                const int ch  = ks * 2 + a_chs;
                const uint32_t off = (uint32_t)((row << 7) + ((ch ^ (row & 7)) << 4));
                ldsm4(afh[mt], stg + off);
                ldsm4(afl[mt], stg + 16384u + off);
            }
            uint32_t bfh[2][4], bfl[2][4];
            #pragma unroll
            for (int np = 0; np < 2; ++np) {
                const int row = b_row + np * 16;
                const int ch  = ks * 2 + b_chs;
                const uint32_t off = (uint32_t)((row << 7) + ((ch ^ (row & 7)) << 4));
                ldsm4(bfh[np], stg + 32768u + off);
                ldsm4(bfl[np], stg + 49152u + off);
            }
            #pragma unroll
            for (int mt = 0; mt < 4; ++mt) {
                #pragma unroll
                for (int nt = 0; nt < 4; ++nt) {
                    const uint32_t* bh = &bfh[nt >> 1][(nt & 1) * 2];
                    const uint32_t* bl = &bfl[nt >> 1][(nt & 1) * 2];
                    mma16816(acc[mt][nt], afh[mt], bh);
                    mma16816(acc[mt][nt], afh[mt], bl);
                    mma16816(acc[mt][nt], afl[mt], bh);
                }
            }
        }

        if (hasNext) {
            char* nst = smx + ((kb + 1) & 1) * MG_STAGE;
            #pragma unroll
            for (int p = 0; p < 4; ++p) {
                const int c = tid + (p << 8);
                const int row = c >> 3, ch = c & 7;
                const int off = (row << 7) + ((ch ^ (row & 7)) << 4);
                *(uint4*)(nst + off)         = vAh[p];
                *(uint4*)(nst + 16384 + off) = vAl[p];
                *(uint4*)(nst + 32768 + off) = vBh[p];
                *(uint4*)(nst + 49152 + off) = vBl[p];
            }
        }
        __syncthreads();
    }

    // epilogue: fragment (mt,nt): c0,c1 -> row lane/4, cols 2*(lane%4)+{0,1};
    //           c2,c3 -> row lane/4+8
    const int erow = lane >> 2;
    const int ecol = (lane & 3) * 2;
    #pragma unroll
    for (int mt = 0; mt < 4; ++mt) {
        #pragma unroll
        for (int nt = 0; nt < 4; ++nt) {
            const size_t gr0 = bm + m0w + mt * 16 + erow;
            const size_t gc  = bn + n0w + nt * 8 + ecol;
            float v0 = acc[mt][nt][0], v1 = acc[mt][nt][1];
            float v2 = acc[mt][nt][2], v3 = acc[mt][nt][3];
            if (do_silu) { v0 = siluf_(v0); v1 = siluf_(v1); v2 = siluf_(v2); v3 = siluf_(v3); }
            if (resid != nullptr) {
                const float2 r0 = *(const float2*)&resid[gr0 * N + gc];
                const float2 r1 = *(const float2*)&resid[(gr0 + 8) * N + gc];
                v0 += r0.x; v1 += r0.y; v2 += r1.x; v3 += r1.y;
            }
            float2 w0; w0.x = v0; w0.y = v1;
            float2 w1; w1.x = v2; w1.y = v3;
            *(float2*)&C[gr0 * N + gc]       = w0;
            *(float2*)&C[(gr0 + 8) * N + gc] = w1;
        }
    }
}

// ---------------------------------------------------------------------------
// 3) beta = sigmoid(normed @ Wb)
// ---------------------------------------------------------------------------
__global__ void __launch_bounds__(256) beta_kernel(const float* __restrict__ Wb) {
    const int warp = (blockIdx.x * blockDim.x + threadIdx.x) >> 5;
    const int lane = threadIdx.x & 31;
    if (warp >= M_) return;
    const float* nr = g_normed + (size_t)warp * D_;
    float a0 = 0, a1 = 0, a2 = 0, a3 = 0;
    for (int d = lane; d < D_; d += 32) {
        const float xn = nr[d];
        const float4 wv = *(const float4*)&Wb[d * 4];
        a0 += xn * wv.x; a1 += xn * wv.y; a2 += xn * wv.z; a3 += xn * wv.w;
    }
    #pragma unroll
    for (int off = 16; off > 0; off >>= 1) {
        a0 += __shfl_xor_sync(0xffffffffu, a0, off);
        a1 += __shfl_xor_sync(0xffffffffu, a1, off);
        a2 += __shfl_xor_sync(0xffffffffu, a2, off);
        a3 += __shfl_xor_sync(0xffffffffu, a3, off);
    }
    if (lane == 0) {
        *(float4*)&g_beta[(size_t)warp * 4] =
            make_float4(sigmoidf_(a0), sigmoidf_(a1), sigmoidf_(a2), sigmoidf_(a3));
    }
}

// ---------------------------------------------------------------------------
// 4) l2norm on q (with DK^-0.5) and k
// ---------------------------------------------------------------------------
__global__ void __launch_bounds__(256) l2norm_kernel() {
    const int grp  = blockIdx.x * 8 + (threadIdx.x >> 5);
    const int lane = threadIdx.x & 31;
    float* base = ((blockIdx.y == 0) ? g_q : g_k) + (size_t)grp * DK_;
    float4 v0 = ((const float4*)base)[lane];
    float4 v1 = ((const float4*)base)[lane + 32];
    float ss = v0.x * v0.x + v0.y * v0.y + v0.z * v0.z + v0.w * v0.w
             + v1.x * v1.x + v1.y * v1.y + v1.z * v1.z + v1.w * v1.w;
    #pragma unroll
    for (int off = 16; off > 0; off >>= 1) ss += __shfl_xor_sync(0xffffffffu, ss, off);
    float sc = rsqrtf(ss + 1e-6f);
    if (blockIdx.y == 0) sc *= 0.0625f;
    v0.x *= sc; v0.y *= sc; v0.z *= sc; v0.w *= sc;
    v1.x *= sc; v1.y *= sc; v1.z *= sc; v1.w *= sc;
    ((float4*)base)[lane]      = v0;
    ((float4*)base)[lane + 32] = v1;
}

// ---------------------------------------------------------------------------
// 5a) prep1 (unchanged from R4)
// ---------------------------------------------------------------------------
#define P1_FLOATS (17408 + 17408 + 4352 + 64)
#define P1_BYTES  (P1_FLOATS * 4)

__global__ void __launch_bounds__(256, 1) prep1_kernel() {
    extern __shared__ float sm1[];
    float* Kt  = sm1;            // [256][68]
    float* wb  = sm1 + 17408;    // [64][260]
    float* Qts = sm1 + 17408;    // [256][68]  (aliases wb)
    float* Ms  = sm1 + 34816;    // [64][68]
    float* bsm = sm1 + 39168;    // [64]

    const int tid  = threadIdx.x;
    const int cIdx = blockIdx.x;
    const int n = cIdx & 31, h = (cIdx >> 5) & 3, b = cIdx >> 7;
    const size_t m0 = (size_t)b * T_ + n * C_;
    const int hK = h * DK_;

    if (tid < 64) bsm[tid] = g_beta[(m0 + tid) * H_ + h];
    __syncthreads();

    #pragma unroll 4
    for (int p = 0; p < 16; ++p) {
        const int idx = tid + p * 256;
        const int i = idx >> 6, c4 = idx & 63;
        const float4 v = *(const float4*)&g_k[(m0 + i) * NKV + hK + c4 * 4];
        Kt[(c4 * 4 + 0) * 68 + i] = v.x;
        Kt[(c4 * 4 + 1) * 68 + i] = v.y;
        Kt[(c4 * 4 + 2) * 68 + i] = v.z;
        Kt[(c4 * 4 + 3) * 68 + i] = v.w;
        const float bb = bsm[i];
        *(float4*)&wb[i * 260 + c4 * 4] = make_float4(v.x * bb, v.y * bb, v.z * bb, v.w * bb);
    }
    __syncthreads();

    const int ty = tid >> 4, tx = tid & 15;
    const int ti4 = ty * 4, tj4 = tx * 4;

    {
        ull acc[4][2] = {};
        #pragma unroll 4
        for (int kk = 0; kk < 256; ++kk) {
            const float4 a4 = *(const float4*)&Kt[kk * 68 + ti4];
            const float4 b4 = *(const float4*)&Kt[kk * 68 + tj4];
            mma4x4p(acc, a4, pack2(b4.x, b4.y), pack2(b4.z, b4.w));
        }
        float mo[4][4]; unp4x4(acc, mo);
        #pragma unroll
        for (int r = 0; r < 4; ++r) {
            const int i = ti4 + r;
            const float bi = bsm[i];
            #pragma unroll
            for (int cc = 0; cc < 4; ++cc) {
                const int j = tj4 + cc;
                Ms[i * 68 + j] = (j < i) ? bi * mo[r][cc] : 0.f;
            }
        }
    }
    __syncthreads();

    for (int i = 1; i < 64; ++i) {
        const float* mr = Ms + i * 68;
        float a0 = 0.f, a1 = 0.f, a2 = 0.f, a3 = 0.f;
        int j = 0;
        for (; j + 4 <= i; j += 4) {
            a0 += mr[j + 0] * wb[(j + 0) * 260 + tid];
            a1 += mr[j + 1] * wb[(j + 1) * 260 + tid];
            a2 += mr[j + 2] * wb[(j + 2) * 260 + tid];
            a3 += mr[j + 3] * wb[(j + 3) * 260 + tid];
        }
        for (; j < i; ++j) a0 += mr[j] * wb[j * 260 + tid];
        wb[i * 260 + tid] -= (a0 + a1) + (a2 + a3);
        __syncthreads();
    }

    {
        float* wt = g_Wt + (size_t)cIdx * (DK_ * C_);
        for (int idx = tid; idx < DK_ * C_; idx += 256) {
            const int kk = idx >> 6, i = idx & 63;
            wt[idx] = wb[i * 260 + kk];
        }
        float* mo = g_mlt + (size_t)cIdx * (C_ * C_);
        for (int idx = tid; idx < C_ * C_; idx += 256)
            mo[idx] = Ms[(idx >> 6) * 68 + (idx & 63)];
    }
    __syncthreads();

    #pragma unroll 4
    for (int p = 0; p < 16; ++p) {
        const int idx = tid + p * 256;
        const int i = idx >> 6, c4 = idx & 63;
        const float4 v = *(const float4*)&g_q[(m0 + i) * NKV + hK + c4 * 4];
        Qts[(c4 * 4 + 0) * 68 + i] = v.x;
        Qts[(c4 * 4 + 1) * 68 + i] = v.y;
        Qts[(c4 * 4 + 2) * 68 + i] = v.z;
        Qts[(c4 * 4 + 3) * 68 + i] = v.w;
    }
    __syncthreads();

    {
        ull acc[4][2] = {};
        #pragma unroll 4
        for (int kk = 0; kk < 256; ++kk) {
            const float4 a4 = *(const float4*)&Qts[kk * 68 + ti4];
            const float4 b4 = *(const float4*)&Kt[kk * 68 + tj4];
            mma4x4p(acc, a4, pack2(b4.x, b4.y), pack2(b4.z, b4.w));
        }
        float po[4][4]; unp4x4(acc, po);
        float* pt = g_Pt + (size_t)cIdx * (C_ * C_);
        #pragma unroll
        for (int cc = 0; cc < 4; ++cc) {
            const int j = tj4 + cc;
            float4 v;
            v.x = (j <= ti4 + 0) ? po[0][cc] : 0.f;
            v.y = (j <= ti4 + 1) ? po[1][cc] : 0.f;
            v.z = (j <= ti4 + 2) ? po[2][cc] : 0.f;
            v.w = (j <= ti4 + 3) ? po[3][cc] : 0.f;
            *(float4*)&pt[j * 64 + ti4] = v;
        }
        float* qt = g_Qt + (size_t)cIdx * (DK_ * C_);
        for (int idx = tid; idx < DK_ * C_; idx += 256)
            qt[idx] = Qts[(idx >> 6) * 68 + (idx & 63)];
    }
}

// ---------------------------------------------------------------------------
// 5b) prep2 (unchanged from R4)
// ---------------------------------------------------------------------------
#define P2_FLOATS (33280 + 4352 + 64)
#define P2_BYTES  (P2_FLOATS * 4)

__global__ void __launch_bounds__(256, 1) prep2_kernel() {
    extern __shared__ float sm2[];
    float* vb  = sm2;            // [64][520]
    float* Ms  = sm2 + 33280;    // [64][68]
    float* bsm = sm2 + 33280 + 4352;

    const int tid  = threadIdx.x;
    const int cIdx = blockIdx.x;
    const int n = cIdx & 31, h = (cIdx >> 5) & 3, b = cIdx >> 7;
    const size_t m0 = (size_t)b * T_ + n * C_;
    const int hV = h * DV_;

    if (tid < 64) bsm[tid] = g_beta[(m0 + tid) * H_ + h];
    {
        const float* mg = g_mlt + (size_t)cIdx * (C_ * C_);
        for (int idx = tid; idx < C_ * C_; idx += 256)
            Ms[(idx >> 6) * 68 + (idx & 63)] = mg[idx];
    }
    __syncthreads();

    #pragma unroll 4
    for (int p = 0; p < 32; ++p) {
        const int idx = tid + p * 256;
        const int i = idx >> 7, c4 = idx & 127;
        float4 v = *(const float4*)&g_v[(m0 + i) * NV + hV + c4 * 4];
        const float bb = bsm[i];
        v.x *= bb; v.y *= bb; v.z *= bb; v.w *= bb;
        *(float4*)&vb[i * 520 + c4 * 4] = v;
    }
    __syncthreads();

    const int col2 = 2 * tid;
    for (int i = 1; i < 64; ++i) {
        const float* mr = Ms + i * 68;
        ull acc = 0ull;
        for (int j = 0; j < i; ++j) {
            const float m = mr[j];
            const ull v = *(const ull*)&vb[j * 520 + col2];
            ffma2(acc, pack2(m, m), v);
        }
        float ax, ay; unpack2(acc, ax, ay);
        vb[i * 520 + col2]     -= ax;
        vb[i * 520 + col2 + 1] -= ay;
        __syncthreads();
    }

    float* uo = g_Uv + (size_t)cIdx * (C_ * DV_);
    #pragma unroll 4
    for (int p = 0; p < 32; ++p) {
        const int idx = tid + p * 256;
        const int i = idx >> 7, c4 = idx & 127;
        *(float4*)&uo[i * DV_ + c4 * 4] = *(const float4*)&vb[i * 520 + c4 * 4];
    }
}

// ---------------------------------------------------------------------------
// 5c) chunkscan (unchanged from R4)
// ---------------------------------------------------------------------------
#define CS_FLOATS (16384 + 4096 * 3 + 4096 * 4)
#define CS_BYTES  (CS_FLOATS * 4)

__global__ void __launch_bounds__(256, 1) chunkscan_kernel() {
    extern __shared__ float sm3[];
    float* S   = sm3;
    float* Ub  = sm3 + 16384;
    float* Pts = sm3 + 20480;
    float* Uvs = sm3 + 24576;
    float* stWb[2] = { sm3 + 28672, sm3 + 32768 };
    float* stQb[2] = { sm3 + 36864, sm3 + 40960 };

    const int tid = threadIdx.x;
    const int c = blockIdx.x & 7, h = (blockIdx.x >> 3) & 3, b = blockIdx.x >> 5;
    const int dv0 = c * 64;
    const int ty = tid >> 4, tx = tid & 15;
    const int ti4 = ty * 4, tj4 = tx * 4;
    const int hK = h * DK_;

    for (int i = tid; i < 16384; i += 256) S[i] = 0.f;

    for (int n = 0; n < NC_; ++n) {
        const int cIdx = b * 128 + h * 32 + n;
        const float* Wt  = g_Wt + (size_t)cIdx * 16384;
        const float* Qt  = g_Qt + (size_t)cIdx * 16384;
        const float* Ptg = g_Pt + (size_t)cIdx * 4096;
        const float* Uvg = g_Uv + (size_t)cIdx * 32768 + dv0;
        const size_t m0  = (size_t)b * T_ + n * 64;

        #pragma unroll
        for (int p = 0; p < 4; ++p) {
            const int idx = tid + p * 256;
            ((float4*)Pts)[idx] = ((const float4*)Ptg)[idx];
            const int r = idx >> 4, c4 = idx & 15;
            ((float4*)Uvs)[idx] = *(const float4*)&Uvg[r * DV_ + c4 * 4];
            ((float4*)stWb[0])[idx] = ((const float4*)Wt)[idx];
            ((float4*)stQb[0])[idx] = ((const float4*)Qt)[idx];
        }
        __syncthreads();

        ull aU[4][2] = {}, aO[4][2] = {};
        int cur = 0;
        for (int kb = 0; kb < 4; ++kb) {
            float4 rw[4], rq[4];
            if (kb < 3) {
                const float4* wsrc = (const float4*)(Wt + (kb + 1) * 4096);
                const float4* qsrc = (const float4*)(Qt + (kb + 1) * 4096);
                #pragma unroll
                for (int p = 0; p < 4; ++p) {
                    rw[p] = wsrc[tid + p * 256];
                    rq[p] = qsrc[tid + p * 256];
                }
            }
            const float* sw = stWb[cur];
            const float* sq = stQb[cur];
            const float* sb = S + kb * 4096;
            #pragma unroll 4
            for (int kk = 0; kk < 64; ++kk) {
                const float4 s4 = *(const float4*)&sb[kk * 64 + tj4];
                const ull b0 = pack2(s4.x, s4.y), b1 = pack2(s4.z, s4.w);
                mma4x4p(aU, *(const float4*)&sw[kk * 64 + ti4], b0, b1);
                mma4x4p(aO, *(const float4*)&sq[kk * 64 + ti4], b0, b1);
            }
            if (kb < 3) {
                #pragma unroll
                for (int p = 0; p < 4; ++p) {
                    ((float4*)stWb[cur ^ 1])[tid + p * 256] = rw[p];
                    ((float4*)stQb[cur ^ 1])[tid + p * 256] = rq[p];
                }
                cur ^= 1;
            }
            __syncthreads();
        }

        {
            float su[4][4]; unp4x4(aU, su);
            #pragma unroll
            for (int r = 0; r < 4; ++r) {
                const float4 uv = *(const float4*)&Uvs[(ti4 + r) * 64 + tj4];
                *(float4*)&Ub[(ti4 + r) * 64 + tj4] =
                    make_float4(uv.x - su[r][0], uv.y - su[r][1],
                                uv.z - su[r][2], uv.w - su[r][3]);
            }
        }
        float4 rk[4];
        #pragma unroll
        for (int p = 0; p < 4; ++p) {
            const int idx = tid + p * 256;
            const int i = idx >> 4, d4 = idx & 15;
            rk[p] = *(const float4*)&g_k[(m0 + i) * NKV + hK + d4 * 4];
        }
        #pragma unroll
        for (int p = 0; p < 4; ++p) ((float4*)stWb[0])[tid + p * 256] = rk[p];
        __syncthreads();

        #pragma unroll 4
        for (int j = 0; j < 64; ++j) {
            const float4 u4 = *(const float4*)&Ub[j * 64 + tj4];
            mma4x4p(aO, *(const float4*)&Pts[j * 64 + ti4],
                    pack2(u4.x, u4.y), pack2(u4.z, u4.w));
        }
        {
            float oo[4][4]; unp4x4(aO, oo);
            #pragma unroll
            for (int r = 0; r < 4; ++r)
                *(float4*)&g_o[(m0 + ti4 + r) * NV + h * DV_ + dv0 + tj4] =
                    make_float4(oo[r][0], oo[r][1], oo[r][2], oo[r][3]);
        }

        int cur2 = 0;
        for (int db = 0; db < 4; ++db) {
            float4 rk2[4];
            if (db < 3) {
                #pragma unroll
                for (int p = 0; p < 4; ++p) {
                    const int idx = tid + p * 256;
                    const int i = idx >> 4, d4 = idx & 15;
                    rk2[p] = *(const float4*)&g_k[(m0 + i) * NKV + hK + (db + 1) * 64 + d4 * 4];
                }
            }
            float* Sb = S + db * 4096;
            ull aS[4][2];
            #pragma unroll
            for (int r = 0; r < 4; ++r) {
                const float4 s4 = *(const float4*)&Sb[(ti4 + r) * 64 + tj4];
                aS[r][0] = pack2(s4.x, s4.y);
                aS[r][1] = pack2(s4.z, s4.w);
            }
            const float* sk = stWb[cur2];
            #pragma unroll 4
            for (int i2 = 0; i2 < 64; ++i2) {
                const float4 u4 = *(const float4*)&Ub[i2 * 64 + tj4];
                mma4x4p(aS, *(const float4*)&sk[i2 * 64 + ti4],
                        pack2(u4.x, u4.y), pack2(u4.z, u4.w));
            }
            {
                float so[4][4]; unp4x4(aS, so);
                #pragma unroll
                for (int r = 0; r < 4; ++r)
                    *(float4*)&Sb[(ti4 + r) * 64 + tj4] =
                        make_float4(so[r][0], so[r][1], so[r][2], so[r][3]);
            }
            if (db < 3) {
                #pragma unroll
                for (int p = 0; p < 4; ++p)
                    ((float4*)stWb[cur2 ^ 1])[tid + p * 256] = rk2[p];
                cur2 ^= 1;
            }
            __syncthreads();
        }
    }
}

// ---------------------------------------------------------------------------
// 6) per-head RMSNorm on g_o -> bf16 split g_oh/g_ol
// ---------------------------------------------------------------------------
__global__ void __launch_bounds__(256) rmsnorm_kernel(const float* __restrict__ w) {
    const int grp  = blockIdx.x * 8 + (threadIdx.x >> 5);
    const int lane = threadIdx.x & 31;
    const float* base = g_o + (size_t)grp * DV_;
    float4 v[4];
    float ss = 0.f;
    #pragma unroll
    for (int i = 0; i < 4; ++i) {
        v[i] = ((const float4*)base)[lane + 32 * i];
        ss += v[i].x * v[i].x + v[i].y * v[i].y + v[i].z * v[i].z + v[i].w * v[i].w;
    }
    #pragma unroll
    for (int off = 16; off > 0; off >>= 1) ss += __shfl_xor_sync(0xffffffffu, ss, off);
    const float rs = rsqrtf(ss * (1.0f / DV_) + 1e-5f);
    #pragma unroll
    for (int i = 0; i < 4; ++i) {
        const int idx = lane + 32 * i;
        const float4 wv = ((const float4*)w)[idx];
        const float4 o = make_float4(v[i].x * rs * wv.x, v[i].y * rs * wv.y,
                                     v[i].z * rs * wv.z, v[i].w * rs * wv.w);
        split_store4(o, g_oh, g_ol, (size_t)grp * DV_ + (size_t)idx * 4);
    }
}

// ---------------------------------------------------------------------------
// Launch
// ---------------------------------------------------------------------------
extern "C" void kernel_launch(void* const* d_in, const int* in_sizes, int n_in,
                              void* d_out, int out_size) {
    const float* x        = (const float*)d_in[0];
    const float* ln_w     = (const float*)d_in[1];
    const float* ln_b     = (const float*)d_in[2];
    const float* Wq       = (const float*)d_in[3];
    const float* Wk       = (const float*)d_in[4];
    const float* Wv       = (const float*)d_in[5];
    const float* Wb       = (const float*)d_in[6];
    const float* o_norm_w = (const float*)d_in[7];
    const float* Wo       = (const float*)d_in[8];
    float* out = (float*)d_out;

    cudaFuncSetAttribute(mma_gemm, cudaFuncAttributeMaxDynamicSharedMemorySize, MG_SMEM);
    cudaFuncSetAttribute(prep1_kernel, cudaFuncAttributeMaxDynamicSharedMemorySize, P1_BYTES);
    cudaFuncSetAttribute(prep2_kernel, cudaFuncAttributeMaxDynamicSharedMemorySize, P2_BYTES);
    cudaFuncSetAttribute(chunkscan_kernel, cudaFuncAttributeMaxDynamicSharedMemorySize, CS_BYTES);

    __nv_bfloat16 *nh, *nl, *oh, *ol, *wqh, *wql, *wkh, *wkl, *wvh, *wvl, *woh, *wol;
    cudaGetSymbolAddress((void**)&nh,  g_nh);
    cudaGetSymbolAddress((void**)&nl,  g_nl);
    cudaGetSymbolAddress((void**)&oh,  g_oh);
    cudaGetSymbolAddress((void**)&ol,  g_ol);
    cudaGetSymbolAddress((void**)&wqh, g_Wqt_h);
    cudaGetSymbolAddress((void**)&wql, g_Wqt_l);
    cudaGetSymbolAddress((void**)&wkh, g_Wkt_h);
    cudaGetSymbolAddress((void**)&wkl, g_Wkt_l);
    cudaGetSymbolAddress((void**)&wvh, g_Wvt_h);
    cudaGetSymbolAddress((void**)&wvl, g_Wvt_l);
    cudaGetSymbolAddress((void**)&woh, g_Wot_h);
    cudaGetSymbolAddress((void**)&wol, g_Wot_l);
    float *gq, *gk, *gv;
    cudaGetSymbolAddress((void**)&gq, g_q);
    cudaGetSymbolAddress((void**)&gk, g_k);
    cudaGetSymbolAddress((void**)&gv, g_v);

    // 1) LayerNorm (+ bf16 split of normed)
    ln_kernel<<<M_, 256>>>(x, ln_w, ln_b);

    // 1b) weight transpose+split
    wtrans_kernel<<<dim3(NKV / 32, D_ / 32), 256>>>(Wq, wqh, wql, D_, NKV);
    wtrans_kernel<<<dim3(NKV / 32, D_ / 32), 256>>>(Wk, wkh, wkl, D_, NKV);
    wtrans_kernel<<<dim3(NV  / 32, D_ / 32), 256>>>(Wv, wvh, wvl, D_, NV);
    wtrans_kernel<<<dim3(D_  / 32, NV / 32), 256>>>(Wo, woh, wol, NV, D_);

    // 2) projections (HMMA, silu fused)
    mma_gemm<<<dim3(NKV / 128, M_ / 128), 256, MG_SMEM>>>(nh, nl, wqh, wql, gq, nullptr, NKV, D_, 1);
    mma_gemm<<<dim3(NKV / 128, M_ / 128), 256, MG_SMEM>>>(nh, nl, wkh, wkl, gk, nullptr, NKV, D_, 1);
    mma_gemm<<<dim3(NV  / 128, M_ / 128), 256, MG_SMEM>>>(nh, nl, wvh, wvl, gv, nullptr, NV,  D_, 1);

    // 3) beta, 4) l2norm
    beta_kernel<<<M_ / 8, 256>>>(Wb);
    l2norm_kernel<<<dim3((M_ * H_) / 8, 2), 256>>>();

    // 5) chunked delta-rule
    prep1_kernel<<<NCH, 256, P1_BYTES>>>();
    prep2_kernel<<<NCH, 256, P2_BYTES>>>();
    chunkscan_kernel<<<B_ * H_ * 8, 256, CS_BYTES>>>();

    // 6) RMSNorm (+ bf16 split of o)
    rmsnorm_kernel<<<(M_ * H_) / 8, 256>>>(o_norm_w);

    // 7) output projection + residual (HMMA)
    mma_gemm<<<dim3(D_ / 128, M_ / 128), 256, MG_SMEM>>>(oh, ol, woh, wol, out, x, D_, NV, 0);
}

// round 8
// speedup vs baseline: 4.2408x; 1.1840x over previous
#include <cuda_runtime.h>
#include <cuda_bf16.h>
#include <cstdint>

// Problem constants (fixed shapes)
#define B_  4
#define T_  2048
#define D_  1024
#define H_  4
#define DK_ 256
#define DV_ 512
#define M_  (B_ * T_)        // 8192 rows
#define NKV (H_ * DK_)       // 1024
#define NV  (H_ * DV_)       // 2048
#define C_   64              // chunk length
#define NC_  32              // chunks per sequence
#define NCH  (B_ * H_ * NC_) // 512 chunk instances

typedef unsigned long long ull;

// ---------------------------------------------------------------------------
// Scratch (device globals; no dynamic allocation allowed)
// ---------------------------------------------------------------------------
__device__ float g_normed[(size_t)M_ * D_];
__device__ float g_q[(size_t)M_ * NKV];
__device__ float g_k[(size_t)M_ * NKV];
__device__ float g_v[(size_t)M_ * NV];
__device__ float g_beta[(size_t)M_ * H_];
__device__ float g_o[(size_t)M_ * NV];
// chunked-scan intermediates
__device__ float g_mlt[(size_t)NCH * C_ * C_];   // [cIdx][i][j]  strict tril
__device__ float g_Uv [(size_t)NCH * C_ * DV_];  // [cIdx][i][dv] fp32
// split-bf16 chunkscan operands (written by prep1)
__device__ __nv_bfloat16 g_cWh [(size_t)NCH * C_ * DK_];  // [cIdx][i][kk]
__device__ __nv_bfloat16 g_cWl [(size_t)NCH * C_ * DK_];
__device__ __nv_bfloat16 g_cQh [(size_t)NCH * C_ * DK_];  // [cIdx][i][kk]
__device__ __nv_bfloat16 g_cQl [(size_t)NCH * C_ * DK_];
__device__ __nv_bfloat16 g_cKth[(size_t)NCH * DK_ * C_];  // [cIdx][kk][i]
__device__ __nv_bfloat16 g_cKtl[(size_t)NCH * DK_ * C_];
__device__ __nv_bfloat16 g_cPh [(size_t)NCH * C_ * C_];   // [cIdx][i][j]
__device__ __nv_bfloat16 g_cPl [(size_t)NCH * C_ * C_];
// bf16 split operands for projection GEMMs
__device__ __nv_bfloat16 g_nh[(size_t)M_ * D_];
__device__ __nv_bfloat16 g_nl[(size_t)M_ * D_];
__device__ __nv_bfloat16 g_oh[(size_t)M_ * NV];
__device__ __nv_bfloat16 g_ol[(size_t)M_ * NV];
__device__ __nv_bfloat16 g_Wqt_h[(size_t)NKV * D_];
__device__ __nv_bfloat16 g_Wqt_l[(size_t)NKV * D_];
__device__ __nv_bfloat16 g_Wkt_h[(size_t)NKV * D_];
__device__ __nv_bfloat16 g_Wkt_l[(size_t)NKV * D_];
__device__ __nv_bfloat16 g_Wvt_h[(size_t)NV * D_];
__device__ __nv_bfloat16 g_Wvt_l[(size_t)NV * D_];
__device__ __nv_bfloat16 g_Wot_h[(size_t)D_ * NV];
__device__ __nv_bfloat16 g_Wot_l[(size_t)D_ * NV];

// ---------------------------------------------------------------------------
// f32x2 packed-FMA helpers (prep kernels)
// ---------------------------------------------------------------------------
__device__ __forceinline__ ull pack2(float x, float y) {
    ull r; asm("mov.b64 %0, {%1, %2};" : "=l"(r) : "f"(x), "f"(y)); return r;
}
__device__ __forceinline__ void unpack2(ull v, float& x, float& y) {
    asm("mov.b64 {%0, %1}, %2;" : "=f"(x), "=f"(y) : "l"(v));
}
__device__ __forceinline__ void ffma2(ull& d, ull a, ull b) {
    asm("fma.rn.f32x2 %0, %1, %2, %0;" : "+l"(d) : "l"(a), "l"(b));
}
__device__ __forceinline__ void mma4x4p(ull (&acc)[4][2], const float4 a4,
                                        const ull b0, const ull b1) {
    ull a;
    a = pack2(a4.x, a4.x); ffma2(acc[0][0], a, b0); ffma2(acc[0][1], a, b1);
    a = pack2(a4.y, a4.y); ffma2(acc[1][0], a, b0); ffma2(acc[1][1], a, b1);
    a = pack2(a4.z, a4.z); ffma2(acc[2][0], a, b0); ffma2(acc[2][1], a, b1);
    a = pack2(a4.w, a4.w); ffma2(acc[3][0], a, b0); ffma2(acc[3][1], a, b1);
}
__device__ __forceinline__ void unp4x4(const ull (&acc)[4][2], float (&o)[4][4]) {
    #pragma unroll
    for (int r = 0; r < 4; ++r) {
        unpack2(acc[r][0], o[r][0], o[r][1]);
        unpack2(acc[r][1], o[r][2], o[r][3]);
    }
}

__device__ __forceinline__ float sigmoidf_(float x) { return 1.0f / (1.0f + __expf(-x)); }
__device__ __forceinline__ float siluf_(float x)    { return x * sigmoidf_(x); }

// split pair (a,b) fp32 -> hi bf16x2 (as u32) + lo bf16x2 (as u32)
__device__ __forceinline__ void split2(float a, float b, uint32_t& hi, uint32_t& lo) {
    __nv_bfloat162 h, l;
    h.x = __float2bfloat16(a); h.y = __float2bfloat16(b);
    l.x = __float2bfloat16(a - __bfloat162float(h.x));
    l.y = __float2bfloat16(b - __bfloat162float(h.y));
    hi = *(uint32_t*)&h; lo = *(uint32_t*)&l;
}

__device__ __forceinline__ void split_store4(const float4 v,
                                             __nv_bfloat16* __restrict__ hp,
                                             __nv_bfloat16* __restrict__ lp,
                                             size_t idx) {
    uint32_t h0, l0, h1, l1;
    split2(v.x, v.y, h0, l0);
    split2(v.z, v.w, h1, l1);
    *(uint32_t*)(hp + idx)     = h0;
    *(uint32_t*)(hp + idx + 2) = h1;
    *(uint32_t*)(lp + idx)     = l0;
    *(uint32_t*)(lp + idx + 2) = l1;
}

// ---------------------------------------------------------------------------
// mma.sync helpers (arch-portable HMMA)
// ---------------------------------------------------------------------------
__device__ __forceinline__ uint32_t smem_u32(const void* p) {
    uint32_t a;
    asm("{ .reg .u64 t; cvta.to.shared.u64 t, %1; cvt.u32.u64 %0, t; }" : "=r"(a) : "l"(p));
    return a;
}
__device__ __forceinline__ void ldsm4(uint32_t* r, uint32_t addr) {
    asm volatile("ldmatrix.sync.aligned.m8n8.x4.shared.b16 {%0,%1,%2,%3}, [%4];"
        : "=r"(r[0]), "=r"(r[1]), "=r"(r[2]), "=r"(r[3]) : "r"(addr));
}
__device__ __forceinline__ void ldsm4t(uint32_t* r, uint32_t addr) {
    asm volatile("ldmatrix.sync.aligned.m8n8.x4.trans.shared.b16 {%0,%1,%2,%3}, [%4];"
        : "=r"(r[0]), "=r"(r[1]), "=r"(r[2]), "=r"(r[3]) : "r"(addr));
}
__device__ __forceinline__ void mma16816(float* c, const uint32_t* a, const uint32_t* b) {
    asm volatile(
        "mma.sync.aligned.m16n8k16.row.col.f32.bf16.bf16.f32 "
        "{%0,%1,%2,%3}, {%4,%5,%6,%7}, {%8,%9}, {%0,%1,%2,%3};"
        : "+f"(c[0]), "+f"(c[1]), "+f"(c[2]), "+f"(c[3])
        : "r"(a[0]), "r"(a[1]), "r"(a[2]), "r"(a[3]), "r"(b[0]), "r"(b[1]));
}

// 64-col bf16 tile swizzle: rows of 128B, 8 chunks of 16B, chunk ^ (row&7)
__device__ __forceinline__ uint32_t swz(int row, int ch) {
    return (uint32_t)((row << 7) + ((ch ^ (row & 7)) << 4));
}
// byte offset of bf16 element (row, col), col even
__device__ __forceinline__ uint32_t swzb(int row, int col) {
    return (uint32_t)((row << 7) + ((((col >> 3) ^ (row & 7))) << 4) + ((col & 7) << 1));
}

// ---------------------------------------------------------------------------
// 1) LayerNorm -> g_normed (fp32) + g_nh/g_nl (bf16 split)
// ---------------------------------------------------------------------------
__global__ void __launch_bounds__(256) ln_kernel(const float* __restrict__ x,
                                                 const float* __restrict__ w,
                                                 const float* __restrict__ b) {
    const int row = blockIdx.x;
    const int tid = threadIdx.x;
    const float4 v = ((const float4*)(x + (size_t)row * D_))[tid];

    float s  = v.x + v.y + v.z + v.w;
    float s2 = v.x * v.x + v.y * v.y + v.z * v.z + v.w * v.w;
    #pragma unroll
    for (int off = 16; off > 0; off >>= 1) {
        s  += __shfl_xor_sync(0xffffffffu, s,  off);
        s2 += __shfl_xor_sync(0xffffffffu, s2, off);
    }
    __shared__ float sh[16];
    const int wid = tid >> 5, lane = tid & 31;
    if (lane == 0) { sh[wid] = s; sh[8 + wid] = s2; }
    __syncthreads();
    float ts = 0.f, ts2 = 0.f;
    #pragma unroll
    for (int i = 0; i < 8; ++i) { ts += sh[i]; ts2 += sh[8 + i]; }

    const float mean = ts * (1.0f / D_);
    const float var  = ts2 * (1.0f / D_) - mean * mean;
    const float rstd = rsqrtf(var + 1e-5f);

    const float4 wv = ((const float4*)w)[tid];
    const float4 bv = ((const float4*)b)[tid];
    float4 o;
    o.x = (v.x - mean) * rstd * wv.x + bv.x;
    o.y = (v.y - mean) * rstd * wv.y + bv.y;
    o.z = (v.z - mean) * rstd * wv.z + bv.z;
    o.w = (v.w - mean) * rstd * wv.w + bv.w;
    const size_t base = (size_t)row * D_;
    ((float4*)(g_normed + base))[tid] = o;
    split_store4(o, g_nh, g_nl, base + (size_t)tid * 4);
}

// ---------------------------------------------------------------------------
// 1b) weight transpose + bf16 split
// ---------------------------------------------------------------------------
__global__ void __launch_bounds__(256) wtrans_kernel(const float* __restrict__ W,
                                                     __nv_bfloat16* __restrict__ Th,
                                                     __nv_bfloat16* __restrict__ Tl,
                                                     int K, int N) {
    __shared__ float tile[32][33];
    const int tx = threadIdx.x & 31, ty = threadIdx.x >> 5;
    const int k0 = blockIdx.y * 32, n0 = blockIdx.x * 32;
    #pragma unroll
    for (int i = 0; i < 32; i += 8)
        tile[ty + i][tx] = W[(size_t)(k0 + ty + i) * N + n0 + tx];
    __syncthreads();
    #pragma unroll
    for (int i = 0; i < 32; i += 8) {
        const float v = tile[tx][ty + i];
        const size_t oi = (size_t)(n0 + ty + i) * K + k0 + tx;
        const __nv_bfloat16 h = __float2bfloat16(v);
        Th[oi] = h;
        Tl[oi] = __float2bfloat16(v - __bfloat162float(h));
    }
}

// ---------------------------------------------------------------------------
// 2) HMMA GEMM (unchanged from R6)
// ---------------------------------------------------------------------------
#define MG_STAGE 65536
#define MG_SMEM  (2 * MG_STAGE)

__global__ void __launch_bounds__(256, 1)
mma_gemm(const __nv_bfloat16* __restrict__ Ah, const __nv_bfloat16* __restrict__ Al,
         const __nv_bfloat16* __restrict__ Bh, const __nv_bfloat16* __restrict__ Bl,
         float* __restrict__ C, const float* __restrict__ resid,
         int N, int K, int do_silu) {
    extern __shared__ char smx[];
    const uint32_t sbase = smem_u32(smx);
    const int tid = threadIdx.x;
    const int lane = tid & 31;
    const int wid = tid >> 5;
    const int wm = wid >> 2;
    const int wn = wid & 3;
    const int m0w = wm * 64, n0w = wn * 32;

    const size_t bm = (size_t)blockIdx.y * 128;
    const size_t bn = (size_t)blockIdx.x * 128;
    const __nv_bfloat16* pAh = Ah + bm * K;
    const __nv_bfloat16* pAl = Al + bm * K;
    const __nv_bfloat16* pBh = Bh + bn * K;
    const __nv_bfloat16* pBl = Bl + bn * K;

    {
        char* stg = smx;
        #pragma unroll
        for (int p = 0; p < 4; ++p) {
            const int c = tid + (p << 8);
            const int row = c >> 3, ch = c & 7;
            const size_t gi = (size_t)row * K + (ch << 3);
            const int off = (row << 7) + (((ch ^ (row & 7))) << 4);
            *(uint4*)(stg + off)         = *(const uint4*)(pAh + gi);
            *(uint4*)(stg + 16384 + off) = *(const uint4*)(pAl + gi);
            *(uint4*)(stg + 32768 + off) = *(const uint4*)(pBh + gi);
            *(uint4*)(stg + 49152 + off) = *(const uint4*)(pBl + gi);
        }
    }
    __syncthreads();

    float acc[4][4][4];
    #pragma unroll
    for (int i = 0; i < 4; ++i)
        #pragma unroll
        for (int j = 0; j < 4; ++j)
            #pragma unroll
            for (int q = 0; q < 4; ++q) acc[i][j][q] = 0.f;

    const int a_row = m0w + (lane & 15);
    const int a_chs = lane >> 4;
    const int b_row = n0w + ((lane >> 3) & 2) * 4 + (lane & 7);
    const int b_chs = (lane >> 3) & 1;

    const int KB = K >> 6;
    for (int kb = 0; kb < KB; ++kb) {
        const uint32_t stg = sbase + (uint32_t)(kb & 1) * MG_STAGE;
        const bool hasNext = (kb + 1) < KB;

        uint4 vAh[4], vAl[4], vBh[4], vBl[4];
        if (hasNext) {
            const int k0 = (kb + 1) << 6;
            #pragma unroll
            for (int p = 0; p < 4; ++p) {
                const int c = tid + (p << 8);
                const int row = c >> 3, ch = c & 7;
                const size_t gi = (size_t)row * K + k0 + (ch << 3);
                vAh[p] = *(const uint4*)(pAh + gi);
                vAl[p] = *(const uint4*)(pAl + gi);
                vBh[p] = *(const uint4*)(pBh + gi);
                vBl[p] = *(const uint4*)(pBl + gi);
            }
        }

        #pragma unroll
        for (int ks = 0; ks < 4; ++ks) {
            uint32_t afh[4][4], afl[4][4];
            #pragma unroll
            for (int mt = 0; mt < 4; ++mt) {
                const int row = a_row + mt * 16;
                const int ch  = ks * 2 + a_chs;
                const uint32_t off = (uint32_t)((row << 7) + ((ch ^ (row & 7)) << 4));
                ldsm4(afh[mt], stg + off);
                ldsm4(afl[mt], stg + 16384u + off);
            }
            uint32_t bfh[2][4], bfl[2][4];
            #pragma unroll
            for (int np = 0; np < 2; ++np) {
                const int row = b_row + np * 16;
                const int ch  = ks * 2 + b_chs;
                const uint32_t off = (uint32_t)((row << 7) + ((ch ^ (row & 7)) << 4));
                ldsm4(bfh[np], stg + 32768u + off);
                ldsm4(bfl[np], stg + 49152u + off);
            }
            #pragma unroll
            for (int mt = 0; mt < 4; ++mt) {
                #pragma unroll
                for (int nt = 0; nt < 4; ++nt) {
                    const uint32_t* bh = &bfh[nt >> 1][(nt & 1) * 2];
                    const uint32_t* bl = &bfl[nt >> 1][(nt & 1) * 2];
                    mma16816(acc[mt][nt], afh[mt], bh);
                    mma16816(acc[mt][nt], afh[mt], bl);
                    mma16816(acc[mt][nt], afl[mt], bh);
                }
            }
        }

        if (hasNext) {
            char* nst = smx + ((kb + 1) & 1) * MG_STAGE;
            #pragma unroll
            for (int p = 0; p < 4; ++p) {
                const int c = tid + (p << 8);
                const int row = c >> 3, ch = c & 7;
                const int off = (row << 7) + ((ch ^ (row & 7)) << 4);
                *(uint4*)(nst + off)         = vAh[p];
                *(uint4*)(nst + 16384 + off) = vAl[p];
                *(uint4*)(nst + 32768 + off) = vBh[p];
                *(uint4*)(nst + 49152 + off) = vBl[p];
            }
        }
        __syncthreads();
    }

    const int erow = lane >> 2;
    const int ecol = (lane & 3) * 2;
    #pragma unroll
    for (int mt = 0; mt < 4; ++mt) {
        #pragma unroll
        for (int nt = 0; nt < 4; ++nt) {
            const size_t gr0 = bm + m0w + mt * 16 + erow;
            const size_t gc  = bn + n0w + nt * 8 + ecol;
            float v0 = acc[mt][nt][0], v1 = acc[mt][nt][1];
            float v2 = acc[mt][nt][2], v3 = acc[mt][nt][3];
            if (do_silu) { v0 = siluf_(v0); v1 = siluf_(v1); v2 = siluf_(v2); v3 = siluf_(v3); }
            if (resid != nullptr) {
                const float2 r0 = *(const float2*)&resid[gr0 * N + gc];
                const float2 r1 = *(const float2*)&resid[(gr0 + 8) * N + gc];
                v0 += r0.x; v1 += r0.y; v2 += r1.x; v3 += r1.y;
            }
            float2 w0; w0.x = v0; w0.y = v1;
            float2 w1; w1.x = v2; w1.y = v3;
            *(float2*)&C[gr0 * N + gc]       = w0;
            *(float2*)&C[(gr0 + 8) * N + gc] = w1;
        }
    }
}

// ---------------------------------------------------------------------------
// 3) beta = sigmoid(normed @ Wb)
// ---------------------------------------------------------------------------
__global__ void __launch_bounds__(256) beta_kernel(const float* __restrict__ Wb) {
    const int warp = (blockIdx.x * blockDim.x + threadIdx.x) >> 5;
    const int lane = threadIdx.x & 31;
    if (warp >= M_) return;
    const float* nr = g_normed + (size_t)warp * D_;
    float a0 = 0, a1 = 0, a2 = 0, a3 = 0;
    for (int d = lane; d < D_; d += 32) {
        const float xn = nr[d];
        const float4 wv = *(const float4*)&Wb[d * 4];
        a0 += xn * wv.x; a1 += xn * wv.y; a2 += xn * wv.z; a3 += xn * wv.w;
    }
    #pragma unroll
    for (int off = 16; off > 0; off >>= 1) {
        a0 += __shfl_xor_sync(0xffffffffu, a0, off);
        a1 += __shfl_xor_sync(0xffffffffu, a1, off);
        a2 += __shfl_xor_sync(0xffffffffu, a2, off);
        a3 += __shfl_xor_sync(0xffffffffu, a3, off);
    }
    if (lane == 0) {
        *(float4*)&g_beta[(size_t)warp * 4] =
            make_float4(sigmoidf_(a0), sigmoidf_(a1), sigmoidf_(a2), sigmoidf_(a3));
    }
}

// ---------------------------------------------------------------------------
// 4) l2norm on q (with DK^-0.5) and k
// ---------------------------------------------------------------------------
__global__ void __launch_bounds__(256) l2norm_kernel() {
    const int grp  = blockIdx.x * 8 + (threadIdx.x >> 5);
    const int lane = threadIdx.x & 31;
    float* base = ((blockIdx.y == 0) ? g_q : g_k) + (size_t)grp * DK_;
    float4 v0 = ((const float4*)base)[lane];
    float4 v1 = ((const float4*)base)[lane + 32];
    float ss = v0.x * v0.x + v0.y * v0.y + v0.z * v0.z + v0.w * v0.w
             + v1.x * v1.x + v1.y * v1.y + v1.z * v1.z + v1.w * v1.w;
    #pragma unroll
    for (int off = 16; off > 0; off >>= 1) ss += __shfl_xor_sync(0xffffffffu, ss, off);
    float sc = rsqrtf(ss + 1e-6f);
    if (blockIdx.y == 0) sc *= 0.0625f;
    v0.x *= sc; v0.y *= sc; v0.z *= sc; v0.w *= sc;
    v1.x *= sc; v1.y *= sc; v1.z *= sc; v1.w *= sc;
    ((float4*)base)[lane]      = v0;
    ((float4*)base)[lane + 32] = v1;
}

// ---------------------------------------------------------------------------
// 5a) prep1: per chunk instance:
//     M  = strict_tril(beta_i * k_i.k_j)        -> g_mlt (fp32, for prep2)
//     W  = (I+M)^{-1} (beta K) -> split bf16 [i][kk]  g_cWh/g_cWl
//     Q  ->                      split bf16 [i][kk]  g_cQh/g_cQl
//     Kt ->                      split bf16 [kk][i]  g_cKth/g_cKtl
//     P  = tril_incl(Q K^T) ->   split bf16 [i][j]   g_cPh/g_cPl
// ---------------------------------------------------------------------------
#define P1_FLOATS (17408 + 17408 + 4352 + 64)
#define P1_BYTES  (P1_FLOATS * 4)

__global__ void __launch_bounds__(256, 1) prep1_kernel() {
    extern __shared__ float sm1[];
    float* Kt  = sm1;            // [256][68]
    float* wb  = sm1 + 17408;    // [64][260]
    float* Qts = sm1 + 17408;    // [256][68]  (aliases wb)
    float* Ms  = sm1 + 34816;    // [64][68]
    float* bsm = sm1 + 39168;    // [64]

    const int tid  = threadIdx.x;
    const int cIdx = blockIdx.x;
    const int n = cIdx & 31, h = (cIdx >> 5) & 3, b = cIdx >> 7;
    const size_t m0 = (size_t)b * T_ + n * C_;
    const int hK = h * DK_;

    if (tid < 64) bsm[tid] = g_beta[(m0 + tid) * H_ + h];
    __syncthreads();

    #pragma unroll 4
    for (int p = 0; p < 16; ++p) {
        const int idx = tid + p * 256;
        const int i = idx >> 6, c4 = idx & 63;
        const float4 v = *(const float4*)&g_k[(m0 + i) * NKV + hK + c4 * 4];
        Kt[(c4 * 4 + 0) * 68 + i] = v.x;
        Kt[(c4 * 4 + 1) * 68 + i] = v.y;
        Kt[(c4 * 4 + 2) * 68 + i] = v.z;
        Kt[(c4 * 4 + 3) * 68 + i] = v.w;
        const float bb = bsm[i];
        *(float4*)&wb[i * 260 + c4 * 4] = make_float4(v.x * bb, v.y * bb, v.z * bb, v.w * bb);
    }
    __syncthreads();

    const int ty = tid >> 4, tx = tid & 15;
    const int ti4 = ty * 4, tj4 = tx * 4;

    // M = beta_i * strict_tril(K K^T)
    {
        ull acc[4][2] = {};
        #pragma unroll 4
        for (int kk = 0; kk < 256; ++kk) {
            const float4 a4 = *(const float4*)&Kt[kk * 68 + ti4];
            const float4 b4 = *(const float4*)&Kt[kk * 68 + tj4];
            mma4x4p(acc, a4, pack2(b4.x, b4.y), pack2(b4.z, b4.w));
        }
        float mo[4][4]; unp4x4(acc, mo);
        #pragma unroll
        for (int r = 0; r < 4; ++r) {
            const int i = ti4 + r;
            const float bi = bsm[i];
            #pragma unroll
            for (int cc = 0; cc < 4; ++cc) {
                const int j = tj4 + cc;
                Ms[i * 68 + j] = (j < i) ? bi * mo[r][cc] : 0.f;
            }
        }
    }

    // Kt split store (pairs over i)
    {
        __nv_bfloat16* kth = g_cKth + (size_t)cIdx * 16384;
        __nv_bfloat16* ktl = g_cKtl + (size_t)cIdx * 16384;
        for (int idx = tid; idx < 8192; idx += 256) {
            const int kk = idx >> 5, i2 = (idx & 31) * 2;
            uint32_t hi, lo;
            split2(Kt[kk * 68 + i2], Kt[kk * 68 + i2 + 1], hi, lo);
            *(uint32_t*)(kth + kk * 64 + i2) = hi;
            *(uint32_t*)(ktl + kk * 64 + i2) = lo;
        }
    }
    __syncthreads();

    // forward substitution: W_i = beta_i k_i - sum_{j<i} M[i][j] W_j
    for (int i = 1; i < 64; ++i) {
        const float* mr = Ms + i * 68;
        float a0 = 0.f, a1 = 0.f, a2 = 0.f, a3 = 0.f;
        int j = 0;
        for (; j + 4 <= i; j += 4) {
            a0 += mr[j + 0] * wb[(j + 0) * 260 + tid];
            a1 += mr[j + 1] * wb[(j + 1) * 260 + tid];
            a2 += mr[j + 2] * wb[(j + 2) * 260 + tid];
            a3 += mr[j + 3] * wb[(j + 3) * 260 + tid];
        }
        for (; j < i; ++j) a0 += mr[j] * wb[j * 260 + tid];
        wb[i * 260 + tid] -= (a0 + a1) + (a2 + a3);
        __syncthreads();
    }

    // store W split [i][kk] + M fp32
    {
        __nv_bfloat16* wh = g_cWh + (size_t)cIdx * 16384;
        __nv_bfloat16* wl = g_cWl + (size_t)cIdx * 16384;
        for (int idx = tid; idx < 8192; idx += 256) {
            const int i = idx >> 7, kk2 = (idx & 127) * 2;
            uint32_t hi, lo;
            split2(wb[i * 260 + kk2], wb[i * 260 + kk2 + 1], hi, lo);
            *(uint32_t*)(wh + i * 256 + kk2) = hi;
            *(uint32_t*)(wl + i * 256 + kk2) = lo;
        }
        float* mo = g_mlt + (size_t)cIdx * (C_ * C_);
        for (int idx = tid; idx < C_ * C_; idx += 256)
            mo[idx] = Ms[(idx >> 6) * 68 + (idx & 63)];
    }
    __syncthreads();   // wb dead; Qts may now overwrite

    // load Q chunk transposed into Qts + split store [i][kk]
    {
        __nv_bfloat16* qh = g_cQh + (size_t)cIdx * 16384;
        __nv_bfloat16* ql = g_cQl + (size_t)cIdx * 16384;
        #pragma unroll 4
        for (int p = 0; p < 16; ++p) {
            const int idx = tid + p * 256;
            const int i = idx >> 6, c4 = idx & 63;
            const float4 v = *(const float4*)&g_q[(m0 + i) * NKV + hK + c4 * 4];
            Qts[(c4 * 4 + 0) * 68 + i] = v.x;
            Qts[(c4 * 4 + 1) * 68 + i] = v.y;
            Qts[(c4 * 4 + 2) * 68 + i] = v.z;
            Qts[(c4 * 4 + 3) * 68 + i] = v.w;
            uint32_t hi, lo;
            split2(v.x, v.y, hi, lo);
            *(uint32_t*)(qh + i * 256 + c4 * 4)     = hi;
            *(uint32_t*)(ql + i * 256 + c4 * 4)     = lo;
            split2(v.z, v.w, hi, lo);
            *(uint32_t*)(qh + i * 256 + c4 * 4 + 2) = hi;
            *(uint32_t*)(ql + i * 256 + c4 * 4 + 2) = lo;
        }
    }
    __syncthreads();

    // P = tril_incl(Q K^T) -> split bf16 [i][j]
    {
        ull acc[4][2] = {};
        #pragma unroll 4
        for (int kk = 0; kk < 256; ++kk) {
            const float4 a4 = *(const float4*)&Qts[kk * 68 + ti4];
            const float4 b4 = *(const float4*)&Kt[kk * 68 + tj4];
            mma4x4p(acc, a4, pack2(b4.x, b4.y), pack2(b4.z, b4.w));
        }
        float po[4][4]; unp4x4(acc, po);
        __nv_bfloat16* ph = g_cPh + (size_t)cIdx * 4096;
        __nv_bfloat16* pl = g_cPl + (size_t)cIdx * 4096;
        #pragma unroll
        for (int r = 0; r < 4; ++r) {
            const int i = ti4 + r;
            const float v0 = (tj4 + 0 <= i) ? po[r][0] : 0.f;
            const float v1 = (tj4 + 1 <= i) ? po[r][1] : 0.f;
            const float v2 = (tj4 + 2 <= i) ? po[r][2] : 0.f;
            const float v3 = (tj4 + 3 <= i) ? po[r][3] : 0.f;
            uint32_t hi, lo;
            split2(v0, v1, hi, lo);
            *(uint32_t*)(ph + i * 64 + tj4)     = hi;
            *(uint32_t*)(pl + i * 64 + tj4)     = lo;
            split2(v2, v3, hi, lo);
            *(uint32_t*)(ph + i * 64 + tj4 + 2) = hi;
            *(uint32_t*)(pl + i * 64 + tj4 + 2) = lo;
        }
    }
}

// ---------------------------------------------------------------------------
// 5b) prep2: Uv = (I+M)^{-1} (beta V)  -> g_Uv (unchanged)
// ---------------------------------------------------------------------------
#define P2_FLOATS (33280 + 4352 + 64)
#define P2_BYTES  (P2_FLOATS * 4)

__global__ void __launch_bounds__(256, 1) prep2_kernel() {
    extern __shared__ float sm2[];
    float* vb  = sm2;            // [64][520]
    float* Ms  = sm2 + 33280;    // [64][68]
    float* bsm = sm2 + 33280 + 4352;

    const int tid  = threadIdx.x;
    const int cIdx = blockIdx.x;
    const int n = cIdx & 31, h = (cIdx >> 5) & 3, b = cIdx >> 7;
    const size_t m0 = (size_t)b * T_ + n * C_;
    const int hV = h * DV_;

    if (tid < 64) bsm[tid] = g_beta[(m0 + tid) * H_ + h];
    {
        const float* mg = g_mlt + (size_t)cIdx * (C_ * C_);
        for (int idx = tid; idx < C_ * C_; idx += 256)
            Ms[(idx >> 6) * 68 + (idx & 63)] = mg[idx];
    }
    __syncthreads();

    #pragma unroll 4
    for (int p = 0; p < 32; ++p) {
        const int idx = tid + p * 256;
        const int i = idx >> 7, c4 = idx & 127;
        float4 v = *(const float4*)&g_v[(m0 + i) * NV + hV + c4 * 4];
        const float bb = bsm[i];
        v.x *= bb; v.y *= bb; v.z *= bb; v.w *= bb;
        *(float4*)&vb[i * 520 + c4 * 4] = v;
    }
    __syncthreads();

    const int col2 = 2 * tid;
    for (int i = 1; i < 64; ++i) {
        const float* mr = Ms + i * 68;
        ull acc = 0ull;
        for (int j = 0; j < i; ++j) {
            const float m = mr[j];
            const ull v = *(const ull*)&vb[j * 520 + col2];
            ffma2(acc, pack2(m, m), v);
        }
        float ax, ay; unpack2(acc, ax, ay);
        vb[i * 520 + col2]     -= ax;
        vb[i * 520 + col2 + 1] -= ay;
        __syncthreads();
    }

    float* uo = g_Uv + (size_t)cIdx * (C_ * DV_);
    #pragma unroll 4
    for (int p = 0; p < 32; ++p) {
        const int idx = tid + p * 256;
        const int i = idx >> 7, c4 = idx & 127;
        *(float4*)&uo[i * DV_ + c4 * 4] = *(const float4*)&vb[i * 520 + c4 * 4];
    }
}

// ---------------------------------------------------------------------------
// 5c) chunkscan v2 (HMMA). 128 CTAs = (b,h,dv-slice 64), 256 thr, 8 warps.
//     Per chunk: U = Uv - W·S ; O = Q·S + P·U ; S += K^T·U
//     S: fp32 master [256][68] + bf16 hi/lo [256][64] (swizzled)
// ---------------------------------------------------------------------------
#define CS2_SH   69632
#define CS2_SL   102400
#define CS2_UH   135168
#define CS2_UL   143360
#define CS2_UVS  151552
#define CS2_STG  168960
#define CS2_BYTES 201728

__global__ void __launch_bounds__(256, 1) chunkscan_kernel() {
    extern __shared__ char sm3[];
    float* SF  = (float*)sm3;                 // [256][68] fp32
    char*  SH  = sm3 + CS2_SH;                // [256][64] bf16 swizzled
    char*  SL  = sm3 + CS2_SL;
    char*  UH  = sm3 + CS2_UH;                // [64][64] bf16 swizzled
    char*  UL  = sm3 + CS2_UL;
    float* UVS = (float*)(sm3 + CS2_UVS);     // [64][68] fp32
    char*  STG = sm3 + CS2_STG;               // 4 x 8192B tiles

    const uint32_t stg_u = smem_u32(STG);
    const uint32_t sh_u  = smem_u32(SH);
    const uint32_t sl_u  = smem_u32(SL);
    const uint32_t uh_u  = smem_u32(UH);
    const uint32_t ul_u  = smem_u32(UL);

    const int tid  = threadIdx.x;
    const int lane = tid & 31, wid = tid >> 5;
    const int wm = wid >> 2, wn = wid & 3;
    const int erow = lane >> 2, ecol = (lane & 3) * 2;
    const int lrow = lane & 15, lhi = lane >> 4;
    const int c = blockIdx.x & 7, h = (blockIdx.x >> 3) & 3, b = blockIdx.x >> 5;
    const int dv0 = c * 64;

    for (int i = tid; i < 17408; i += 256) SF[i] = 0.f;
    for (int i = tid; i < 8192; i += 256) { ((uint32_t*)SH)[i] = 0u; ((uint32_t*)SL)[i] = 0u; }
    __syncthreads();

    for (int n = 0; n < NC_; ++n) {
        const int cIdx = b * 128 + h * 32 + n;
        const __nv_bfloat16* Wh  = g_cWh  + (size_t)cIdx * 16384;
        const __nv_bfloat16* Wl  = g_cWl  + (size_t)cIdx * 16384;
        const __nv_bfloat16* Qh  = g_cQh  + (size_t)cIdx * 16384;
        const __nv_bfloat16* Ql  = g_cQl  + (size_t)cIdx * 16384;
        const __nv_bfloat16* Kth = g_cKth + (size_t)cIdx * 16384;
        const __nv_bfloat16* Ktl = g_cKtl + (size_t)cIdx * 16384;
        const __nv_bfloat16* Ph  = g_cPh  + (size_t)cIdx * 4096;
        const __nv_bfloat16* Pl  = g_cPl  + (size_t)cIdx * 4096;
        const float* Uvg = g_Uv + (size_t)cIdx * 32768 + dv0;
        const size_t m0  = (size_t)b * T_ + n * 64;

        // stage W/Q block 0 + Uv
        #pragma unroll
        for (int j = 0; j < 2; ++j) {
            const int idx = tid + j * 256;
            const int r = idx >> 3, ch = idx & 7;
            const uint32_t so = swz(r, ch);
            const size_t gi = (size_t)r * 256 + ch * 8;
            *(uint4*)(STG + so)         = *(const uint4*)(Wh + gi);
            *(uint4*)(STG + 8192 + so)  = *(const uint4*)(Wl + gi);
            *(uint4*)(STG + 16384 + so) = *(const uint4*)(Qh + gi);
            *(uint4*)(STG + 24576 + so) = *(const uint4*)(Ql + gi);
        }
        #pragma unroll
        for (int j = 0; j < 4; ++j) {
            const int idx = tid + j * 256;
            const int r = idx >> 4, c4 = idx & 15;
            *(float4*)&UVS[r * 68 + c4 * 4] = *(const float4*)&Uvg[(size_t)r * DV_ + c4 * 4];
        }
        __syncthreads();

        float accU[2][2][4] = {}, accO[2][2][4] = {};

        // GEMM1+2a: accU = W·S, accO = Q·S over 4 kk-blocks
        for (int kb = 0; kb < 4; ++kb) {
            uint4 pf[8];
            if (kb < 3) {
                #pragma unroll
                for (int j = 0; j < 2; ++j) {
                    const int idx = tid + j * 256;
                    const int r = idx >> 3, ch = idx & 7;
                    const size_t gi = (size_t)r * 256 + (kb + 1) * 64 + ch * 8;
                    pf[j]     = *(const uint4*)(Wh + gi);
                    pf[2 + j] = *(const uint4*)(Wl + gi);
                    pf[4 + j] = *(const uint4*)(Qh + gi);
                    pf[6 + j] = *(const uint4*)(Ql + gi);
                }
            }
            #pragma unroll
            for (int ks = 0; ks < 4; ++ks) {
                uint32_t wfh[2][4], wfl[2][4], qfh[2][4], qfl[2][4];
                #pragma unroll
                for (int mt = 0; mt < 2; ++mt) {
                    const int ar = wm * 32 + mt * 16 + lrow;
                    const uint32_t ao = swz(ar, ks * 2 + lhi);
                    ldsm4(wfh[mt], stg_u + ao);
                    ldsm4(wfl[mt], stg_u + 8192u + ao);
                    ldsm4(qfh[mt], stg_u + 16384u + ao);
                    ldsm4(qfl[mt], stg_u + 24576u + ao);
                }
                uint32_t sfh[4], sfl[4];
                const int br = kb * 64 + ks * 16 + lrow;
                const uint32_t bo = swz(br, wn * 2 + lhi);
                ldsm4t(sfh, sh_u + bo);
                ldsm4t(sfl, sl_u + bo);
                #pragma unroll
                for (int mt = 0; mt < 2; ++mt)
                    #pragma unroll
                    for (int nt = 0; nt < 2; ++nt) {
                        mma16816(accU[mt][nt], wfh[mt], sfh + nt * 2);
                        mma16816(accU[mt][nt], wfh[mt], sfl + nt * 2);
                        mma16816(accU[mt][nt], wfl[mt], sfh + nt * 2);
                        mma16816(accO[mt][nt], qfh[mt], sfh + nt * 2);
                        mma16816(accO[mt][nt], qfh[mt], sfl + nt * 2);
                        mma16816(accO[mt][nt], qfl[mt], sfh + nt * 2);
                    }
            }
            __syncthreads();
            if (kb < 3) {
                #pragma unroll
                for (int j = 0; j < 2; ++j) {
                    const int idx = tid + j * 256;
                    const int r = idx >> 3, ch = idx & 7;
                    const uint32_t so = swz(r, ch);
                    *(uint4*)(STG + so)         = pf[j];
                    *(uint4*)(STG + 8192 + so)  = pf[2 + j];
                    *(uint4*)(STG + 16384 + so) = pf[4 + j];
                    *(uint4*)(STG + 24576 + so) = pf[6 + j];
                }
                __syncthreads();
            }
        }

        // U finalize (u = Uv - accU) -> UH/UL ; load P -> T0/T1, Kt block0 -> T2/T3
        #pragma unroll
        for (int mt = 0; mt < 2; ++mt)
            #pragma unroll
            for (int nt = 0; nt < 2; ++nt) {
                const int r0 = wm * 32 + mt * 16 + erow;
                const int cc = wn * 16 + nt * 8 + ecol;
                const float u0 = UVS[r0 * 68 + cc]           - accU[mt][nt][0];
                const float u1 = UVS[r0 * 68 + cc + 1]       - accU[mt][nt][1];
                const float u2 = UVS[(r0 + 8) * 68 + cc]     - accU[mt][nt][2];
                const float u3 = UVS[(r0 + 8) * 68 + cc + 1] - accU[mt][nt][3];
                uint32_t hi, lo;
                split2(u0, u1, hi, lo);
                *(uint32_t*)(UH + swzb(r0, cc)) = hi;
                *(uint32_t*)(UL + swzb(r0, cc)) = lo;
                split2(u2, u3, hi, lo);
                *(uint32_t*)(UH + swzb(r0 + 8, cc)) = hi;
                *(uint32_t*)(UL + swzb(r0 + 8, cc)) = lo;
            }
        #pragma unroll
        for (int j = 0; j < 2; ++j) {
            const int idx = tid + j * 256;
            const int r = idx >> 3, ch = idx & 7;
            const uint32_t so = swz(r, ch);
            const size_t gp = (size_t)r * 64 + ch * 8;
            *(uint4*)(STG + so)         = *(const uint4*)(Ph + gp);
            *(uint4*)(STG + 8192 + so)  = *(const uint4*)(Pl + gp);
            *(uint4*)(STG + 16384 + so) = *(const uint4*)(Kth + gp);   // Kt rows 0..63
            *(uint4*)(STG + 24576 + so) = *(const uint4*)(Ktl + gp);
        }
        __syncthreads();

        // hoist U B-fragments for all 4 k-steps (shared by GEMM2b and GEMM3)
        uint32_t ufh[4][4], ufl[4][4];
        #pragma unroll
        for (int ks = 0; ks < 4; ++ks) {
            const int br = ks * 16 + lrow;
            const uint32_t bo = swz(br, wn * 2 + lhi);
            ldsm4t(ufh[ks], uh_u + bo);
            ldsm4t(ufl[ks], ul_u + bo);
        }

        // GEMM2b: accO += P·U
        #pragma unroll
        for (int ks = 0; ks < 4; ++ks) {
            uint32_t pfh[2][4], pfl[2][4];
            #pragma unroll
            for (int mt = 0; mt < 2; ++mt) {
                const int ar = wm * 32 + mt * 16 + lrow;
                const uint32_t ao = swz(ar, ks * 2 + lhi);
                ldsm4(pfh[mt], stg_u + ao);
                ldsm4(pfl[mt], stg_u + 8192u + ao);
            }
            #pragma unroll
            for (int mt = 0; mt < 2; ++mt)
                #pragma unroll
                for (int nt = 0; nt < 2; ++nt) {
                    mma16816(accO[mt][nt], pfh[mt], ufh[ks] + nt * 2);
                    mma16816(accO[mt][nt], pfh[mt], ufl[ks] + nt * 2);
                    mma16816(accO[mt][nt], pfl[mt], ufh[ks] + nt * 2);
                }
        }

        // O epilogue -> global
        #pragma unroll
        for (int mt = 0; mt < 2; ++mt)
            #pragma unroll
            for (int nt = 0; nt < 2; ++nt) {
                const int r0 = wm * 32 + mt * 16 + erow;
                const int cc = wn * 16 + nt * 8 + ecol;
                float2 w0; w0.x = accO[mt][nt][0]; w0.y = accO[mt][nt][1];
                float2 w1; w1.x = accO[mt][nt][2]; w1.y = accO[mt][nt][3];
                *(float2*)&g_o[(m0 + r0) * NV + h * DV_ + dv0 + cc]     = w0;
                *(float2*)&g_o[(m0 + r0 + 8) * NV + h * DV_ + dv0 + cc] = w1;
            }
        __syncthreads();   // retire P reads (T0/T1) before GEMM3 stores there

        // GEMM3: S += K^T · U, 4 kk-blocks, double-buffered halves
        for (int kkb = 0; kkb < 4; ++kkb) {
            float accS[2][2][4] = {};
            uint4 kf[4];
            if (kkb < 3) {
                #pragma unroll
                for (int j = 0; j < 2; ++j) {
                    const int idx = tid + j * 256;
                    const int r = idx >> 3, ch = idx & 7;
                    const size_t gi = (size_t)((kkb + 1) * 64 + r) * 64 + ch * 8;
                    kf[j]     = *(const uint4*)(Kth + gi);
                    kf[2 + j] = *(const uint4*)(Ktl + gi);
                }
            }
            const uint32_t curH = stg_u + ((kkb & 1) ? 0u : 16384u);
            const uint32_t curL = stg_u + ((kkb & 1) ? 8192u : 24576u);
            #pragma unroll
            for (int ks = 0; ks < 4; ++ks) {
                uint32_t kfh[2][4], kfl[2][4];
                #pragma unroll
                for (int mt = 0; mt < 2; ++mt) {
                    const int ar = wm * 32 + mt * 16 + lrow;
                    const uint32_t ao = swz(ar, ks * 2 + lhi);
                    ldsm4(kfh[mt], curH + ao);
                    ldsm4(kfl[mt], curL + ao);
                }
                #pragma unroll
                for (int mt = 0; mt < 2; ++mt)
                    #pragma unroll
                    for (int nt = 0; nt < 2; ++nt) {
                        mma16816(accS[mt][nt], kfh[mt], ufh[ks] + nt * 2);
                        mma16816(accS[mt][nt], kfh[mt], ufl[ks] + nt * 2);
                        mma16816(accS[mt][nt], kfl[mt], ufh[ks] + nt * 2);
                    }
            }
            // S finalize: fp32 RMW + bf16 re-split for this 64-row block
            #pragma unroll
            for (int mt = 0; mt < 2; ++mt)
                #pragma unroll
                for (int nt = 0; nt < 2; ++nt) {
                    const int sr = kkb * 64 + wm * 32 + mt * 16 + erow;
                    const int sc = wn * 16 + nt * 8 + ecol;
                    const float s0 = SF[sr * 68 + sc]           + accS[mt][nt][0];
                    const float s1 = SF[sr * 68 + sc + 1]       + accS[mt][nt][1];
                    const float s2 = SF[(sr + 8) * 68 + sc]     + accS[mt][nt][2];
                    const float s3 = SF[(sr + 8) * 68 + sc + 1] + accS[mt][nt][3];
                    SF[sr * 68 + sc]           = s0;
                    SF[sr * 68 + sc + 1]       = s1;
                    SF[(sr + 8) * 68 + sc]     = s2;
                    SF[(sr + 8) * 68 + sc + 1] = s3;
                    uint32_t hi, lo;
                    split2(s0, s1, hi, lo);
                    *(uint32_t*)(SH + swzb(sr, sc)) = hi;
                    *(uint32_t*)(SL + swzb(sr, sc)) = lo;
                    split2(s2, s3, hi, lo);
                    *(uint32_t*)(SH + swzb(sr + 8, sc)) = hi;
                    *(uint32_t*)(SL + swzb(sr + 8, sc)) = lo;
                }
            __syncthreads();
            if (kkb < 3) {
                char* oH = STG + ((kkb & 1) ? 16384 : 0);
                char* oL = STG + ((kkb & 1) ? 24576 : 8192);
                #pragma unroll
                for (int j = 0; j < 2; ++j) {
                    const int idx = tid + j * 256;
                    const int r = idx >> 3, ch = idx & 7;
                    const uint32_t so = swz(r, ch);
                    *(uint4*)(oH + so) = kf[j];
                    *(uint4*)(oL + so) = kf[2 + j];
                }
                __syncthreads();
            }
        }
    }
}

// ---------------------------------------------------------------------------
// 6) per-head RMSNorm on g_o -> bf16 split g_oh/g_ol
// ---------------------------------------------------------------------------
__global__ void __launch_bounds__(256) rmsnorm_kernel(const float* __restrict__ w) {
    const int grp  = blockIdx.x * 8 + (threadIdx.x >> 5);
    const int lane = threadIdx.x & 31;
    const float* base = g_o + (size_t)grp * DV_;
    float4 v[4];
    float ss = 0.f;
    #pragma unroll
    for (int i = 0; i < 4; ++i) {
        v[i] = ((const float4*)base)[lane + 32 * i];
        ss += v[i].x * v[i].x + v[i].y * v[i].y + v[i].z * v[i].z + v[i].w * v[i].w;
    }
    #pragma unroll
    for (int off = 16; off > 0; off >>= 1) ss += __shfl_xor_sync(0xffffffffu, ss, off);
    const float rs = rsqrtf(ss * (1.0f / DV_) + 1e-5f);
    #pragma unroll
    for (int i = 0; i < 4; ++i) {
        const int idx = lane + 32 * i;
        const float4 wv = ((const float4*)w)[idx];
        const float4 o = make_float4(v[i].x * rs * wv.x, v[i].y * rs * wv.y,
                                     v[i].z * rs * wv.z, v[i].w * rs * wv.w);
        split_store4(o, g_oh, g_ol, (size_t)grp * DV_ + (size_t)idx * 4);
    }
}

// ---------------------------------------------------------------------------
// Launch
// ---------------------------------------------------------------------------
extern "C" void kernel_launch(void* const* d_in, const int* in_sizes, int n_in,
                              void* d_out, int out_size) {
    const float* x        = (const float*)d_in[0];
    const float* ln_w     = (const float*)d_in[1];
    const float* ln_b     = (const float*)d_in[2];
    const float* Wq       = (const float*)d_in[3];
    const float* Wk       = (const float*)d_in[4];
    const float* Wv       = (const float*)d_in[5];
    const float* Wb       = (const float*)d_in[6];
    const float* o_norm_w = (const float*)d_in[7];
    const float* Wo       = (const float*)d_in[8];
    float* out = (float*)d_out;

    cudaFuncSetAttribute(mma_gemm, cudaFuncAttributeMaxDynamicSharedMemorySize, MG_SMEM);
    cudaFuncSetAttribute(prep1_kernel, cudaFuncAttributeMaxDynamicSharedMemorySize, P1_BYTES);
    cudaFuncSetAttribute(prep2_kernel, cudaFuncAttributeMaxDynamicSharedMemorySize, P2_BYTES);
    cudaFuncSetAttribute(chunkscan_kernel, cudaFuncAttributeMaxDynamicSharedMemorySize, CS2_BYTES);

    __nv_bfloat16 *nh, *nl, *oh, *ol, *wqh, *wql, *wkh, *wkl, *wvh, *wvl, *woh, *wol;
    cudaGetSymbolAddress((void**)&nh,  g_nh);
    cudaGetSymbolAddress((void**)&nl,  g_nl);
    cudaGetSymbolAddress((void**)&oh,  g_oh);
    cudaGetSymbolAddress((void**)&ol,  g_ol);
    cudaGetSymbolAddress((void**)&wqh, g_Wqt_h);
    cudaGetSymbolAddress((void**)&wql, g_Wqt_l);
    cudaGetSymbolAddress((void**)&wkh, g_Wkt_h);
    cudaGetSymbolAddress((void**)&wkl, g_Wkt_l);
    cudaGetSymbolAddress((void**)&wvh, g_Wvt_h);
    cudaGetSymbolAddress((void**)&wvl, g_Wvt_l);
    cudaGetSymbolAddress((void**)&woh, g_Wot_h);
    cudaGetSymbolAddress((void**)&wol, g_Wot_l);
    float *gq, *gk, *gv;
    cudaGetSymbolAddress((void**)&gq, g_q);
    cudaGetSymbolAddress((void**)&gk, g_k);
    cudaGetSymbolAddress((void**)&gv, g_v);

    // 1) LayerNorm (+ bf16 split of normed)
    ln_kernel<<<M_, 256>>>(x, ln_w, ln_b);

    // 1b) weight transpose+split
    wtrans_kernel<<<dim3(NKV / 32, D_ / 32), 256>>>(Wq, wqh, wql, D_, NKV);
    wtrans_kernel<<<dim3(NKV / 32, D_ / 32), 256>>>(Wk, wkh, wkl, D_, NKV);
    wtrans_kernel<<<dim3(NV  / 32, D_ / 32), 256>>>(Wv, wvh, wvl, D_, NV);
    wtrans_kernel<<<dim3(D_  / 32, NV / 32), 256>>>(Wo, woh, wol, NV, D_);

    // 2) projections (HMMA, silu fused)
    mma_gemm<<<dim3(NKV / 128, M_ / 128), 256, MG_SMEM>>>(nh, nl, wqh, wql, gq, nullptr, NKV, D_, 1);
    mma_gemm<<<dim3(NKV / 128, M_ / 128), 256, MG_SMEM>>>(nh, nl, wkh, wkl, gk, nullptr, NKV, D_, 1);
    mma_gemm<<<dim3(NV  / 128, M_ / 128), 256, MG_SMEM>>>(nh, nl, wvh, wvl, gv, nullptr, NV,  D_, 1);

    // 3) beta, 4) l2norm
    beta_kernel<<<M_ / 8, 256>>>(Wb);
    l2norm_kernel<<<dim3((M_ * H_) / 8, 2), 256>>>();

    // 5) chunked delta-rule
    prep1_kernel<<<NCH, 256, P1_BYTES>>>();
    prep2_kernel<<<NCH, 256, P2_BYTES>>>();
    chunkscan_kernel<<<B_ * H_ * 8, 256, CS2_BYTES>>>();

    // 6) RMSNorm (+ bf16 split of o)
    rmsnorm_kernel<<<(M_ * H_) / 8, 256>>>(o_norm_w);

    // 7) output projection + residual (HMMA)
    mma_gemm<<<dim3(D_ / 128, M_ / 128), 256, MG_SMEM>>>(oh, ol, woh, wol, out, x, D_, NV, 0);
}

// round 9
// speedup vs baseline: 4.2969x; 1.0132x over previous
#include <cuda_runtime.h>
#include <cuda_bf16.h>
#include <cstdint>

// Problem constants (fixed shapes)
#define B_  4
#define T_  2048
#define D_  1024
#define H_  4
#define DK_ 256
#define DV_ 512
#define M_  (B_ * T_)        // 8192 rows
#define NKV (H_ * DK_)       // 1024
#define NV  (H_ * DV_)       // 2048
#define C_   64              // chunk length
#define NC_  32              // chunks per sequence
#define NCH  (B_ * H_ * NC_) // 512 chunk instances

typedef unsigned long long ull;

// ---------------------------------------------------------------------------
// Scratch (device globals; no dynamic allocation allowed)
// ---------------------------------------------------------------------------
__device__ float g_q[(size_t)M_ * NKV];
__device__ float g_k[(size_t)M_ * NKV];
__device__ float g_v[(size_t)M_ * NV];
__device__ float g_beta[(size_t)M_ * H_];
__device__ float g_o[(size_t)M_ * NV];
// chunked-scan intermediates
__device__ float g_mlt[(size_t)NCH * C_ * C_];   // [cIdx][i][j]  strict tril
__device__ float g_Uv [(size_t)NCH * C_ * DV_];  // [cIdx][i][dv] fp32
// split-bf16 chunkscan operands (written by prep1)
__device__ __nv_bfloat16 g_cWh [(size_t)NCH * C_ * DK_];  // [cIdx][i][kk]
__device__ __nv_bfloat16 g_cWl [(size_t)NCH * C_ * DK_];
__device__ __nv_bfloat16 g_cQh [(size_t)NCH * C_ * DK_];  // [cIdx][i][kk]
__device__ __nv_bfloat16 g_cQl [(size_t)NCH * C_ * DK_];
__device__ __nv_bfloat16 g_cKth[(size_t)NCH * DK_ * C_];  // [cIdx][kk][i]
__device__ __nv_bfloat16 g_cKtl[(size_t)NCH * DK_ * C_];
__device__ __nv_bfloat16 g_cPh [(size_t)NCH * C_ * C_];   // [cIdx][i][j]
__device__ __nv_bfloat16 g_cPl [(size_t)NCH * C_ * C_];
// bf16 split operands for projection GEMMs
__device__ __nv_bfloat16 g_nh[(size_t)M_ * D_];
__device__ __nv_bfloat16 g_nl[(size_t)M_ * D_];
__device__ __nv_bfloat16 g_oh[(size_t)M_ * NV];
__device__ __nv_bfloat16 g_ol[(size_t)M_ * NV];
__device__ __nv_bfloat16 g_Wqt_h[(size_t)NKV * D_];
__device__ __nv_bfloat16 g_Wqt_l[(size_t)NKV * D_];
__device__ __nv_bfloat16 g_Wkt_h[(size_t)NKV * D_];
__device__ __nv_bfloat16 g_Wkt_l[(size_t)NKV * D_];
__device__ __nv_bfloat16 g_Wvt_h[(size_t)NV * D_];
__device__ __nv_bfloat16 g_Wvt_l[(size_t)NV * D_];
__device__ __nv_bfloat16 g_Wot_h[(size_t)D_ * NV];
__device__ __nv_bfloat16 g_Wot_l[(size_t)D_ * NV];

// ---------------------------------------------------------------------------
// f32x2 packed-FMA helpers (prep kernels)
// ---------------------------------------------------------------------------
__device__ __forceinline__ ull pack2(float x, float y) {
    ull r; asm("mov.b64 %0, {%1, %2};" : "=l"(r) : "f"(x), "f"(y)); return r;
}
__device__ __forceinline__ void unpack2(ull v, float& x, float& y) {
    asm("mov.b64 {%0, %1}, %2;" : "=f"(x), "=f"(y) : "l"(v));
}
__device__ __forceinline__ void ffma2(ull& d, ull a, ull b) {
    asm("fma.rn.f32x2 %0, %1, %2, %0;" : "+l"(d) : "l"(a), "l"(b));
}
__device__ __forceinline__ void mma4x4p(ull (&acc)[4][2], const float4 a4,
                                        const ull b0, const ull b1) {
    ull a;
    a = pack2(a4.x, a4.x); ffma2(acc[0][0], a, b0); ffma2(acc[0][1], a, b1);
    a = pack2(a4.y, a4.y); ffma2(acc[1][0], a, b0); ffma2(acc[1][1], a, b1);
    a = pack2(a4.z, a4.z); ffma2(acc[2][0], a, b0); ffma2(acc[2][1], a, b1);
    a = pack2(a4.w, a4.w); ffma2(acc[3][0], a, b0); ffma2(acc[3][1], a, b1);
}
__device__ __forceinline__ void unp4x4(const ull (&acc)[4][2], float (&o)[4][4]) {
    #pragma unroll
    for (int r = 0; r < 4; ++r) {
        unpack2(acc[r][0], o[r][0], o[r][1]);
        unpack2(acc[r][1], o[r][2], o[r][3]);
    }
}

__device__ __forceinline__ float sigmoidf_(float x) { return 1.0f / (1.0f + __expf(-x)); }
__device__ __forceinline__ float siluf_(float x)    { return x * sigmoidf_(x); }

// split pair (a,b) fp32 -> hi bf16x2 (as u32) + lo bf16x2 (as u32)
__device__ __forceinline__ void split2(float a, float b, uint32_t& hi, uint32_t& lo) {
    __nv_bfloat162 h, l;
    h.x = __float2bfloat16(a); h.y = __float2bfloat16(b);
    l.x = __float2bfloat16(a - __bfloat162float(h.x));
    l.y = __float2bfloat16(b - __bfloat162float(h.y));
    hi = *(uint32_t*)&h; lo = *(uint32_t*)&l;
}

__device__ __forceinline__ void split_store4(const float4 v,
                                             __nv_bfloat16* __restrict__ hp,
                                             __nv_bfloat16* __restrict__ lp,
                                             size_t idx) {
    uint32_t h0, l0, h1, l1;
    split2(v.x, v.y, h0, l0);
    split2(v.z, v.w, h1, l1);
    *(uint32_t*)(hp + idx)     = h0;
    *(uint32_t*)(hp + idx + 2) = h1;
    *(uint32_t*)(lp + idx)     = l0;
    *(uint32_t*)(lp + idx + 2) = l1;
}

// ---------------------------------------------------------------------------
// mma.sync helpers (arch-portable HMMA)
// ---------------------------------------------------------------------------
__device__ __forceinline__ uint32_t smem_u32(const void* p) {
    uint32_t a;
    asm("{ .reg .u64 t; cvta.to.shared.u64 t, %1; cvt.u32.u64 %0, t; }" : "=r"(a) : "l"(p));
    return a;
}
__device__ __forceinline__ void ldsm4(uint32_t* r, uint32_t addr) {
    asm volatile("ldmatrix.sync.aligned.m8n8.x4.shared.b16 {%0,%1,%2,%3}, [%4];"
        : "=r"(r[0]), "=r"(r[1]), "=r"(r[2]), "=r"(r[3]) : "r"(addr));
}
__device__ __forceinline__ void ldsm4t(uint32_t* r, uint32_t addr) {
    asm volatile("ldmatrix.sync.aligned.m8n8.x4.trans.shared.b16 {%0,%1,%2,%3}, [%4];"
        : "=r"(r[0]), "=r"(r[1]), "=r"(r[2]), "=r"(r[3]) : "r"(addr));
}
__device__ __forceinline__ void mma16816(float* c, const uint32_t* a, const uint32_t* b) {
    asm volatile(
        "mma.sync.aligned.m16n8k16.row.col.f32.bf16.bf16.f32 "
        "{%0,%1,%2,%3}, {%4,%5,%6,%7}, {%8,%9}, {%0,%1,%2,%3};"
        : "+f"(c[0]), "+f"(c[1]), "+f"(c[2]), "+f"(c[3])
        : "r"(a[0]), "r"(a[1]), "r"(a[2]), "r"(a[3]), "r"(b[0]), "r"(b[1]));
}

// 64-col bf16 tile swizzle: rows of 128B, 8 chunks of 16B, chunk ^ (row&7)
__device__ __forceinline__ uint32_t swz(int row, int ch) {
    return (uint32_t)((row << 7) + ((ch ^ (row & 7)) << 4));
}
// byte offset of bf16 element (row, col), col even
__device__ __forceinline__ uint32_t swzb(int row, int col) {
    return (uint32_t)((row << 7) + ((((col >> 3) ^ (row & 7))) << 4) + ((col & 7) << 1));
}

// ---------------------------------------------------------------------------
// 1) LayerNorm -> g_nh/g_nl (bf16 split) + fused beta = sigmoid(normed @ Wb)
// ---------------------------------------------------------------------------
__global__ void __launch_bounds__(256) ln_kernel(const float* __restrict__ x,
                                                 const float* __restrict__ w,
                                                 const float* __restrict__ b,
                                                 const float* __restrict__ Wb) {
    const int row = blockIdx.x;
    const int tid = threadIdx.x;
    const float4 v = ((const float4*)(x + (size_t)row * D_))[tid];

    float s  = v.x + v.y + v.z + v.w;
    float s2 = v.x * v.x + v.y * v.y + v.z * v.z + v.w * v.w;
    #pragma unroll
    for (int off = 16; off > 0; off >>= 1) {
        s  += __shfl_xor_sync(0xffffffffu, s,  off);
        s2 += __shfl_xor_sync(0xffffffffu, s2, off);
    }
    __shared__ float sh[16];
    __shared__ float bsh[32];
    const int wid = tid >> 5, lane = tid & 31;
    if (lane == 0) { sh[wid] = s; sh[8 + wid] = s2; }
    __syncthreads();
    float ts = 0.f, ts2 = 0.f;
    #pragma unroll
    for (int i = 0; i < 8; ++i) { ts += sh[i]; ts2 += sh[8 + i]; }

    const float mean = ts * (1.0f / D_);
    const float var  = ts2 * (1.0f / D_) - mean * mean;
    const float rstd = rsqrtf(var + 1e-5f);

    const float4 wv = ((const float4*)w)[tid];
    const float4 bv = ((const float4*)b)[tid];
    float4 o;
    o.x = (v.x - mean) * rstd * wv.x + bv.x;
    o.y = (v.y - mean) * rstd * wv.y + bv.y;
    o.z = (v.z - mean) * rstd * wv.z + bv.z;
    o.w = (v.w - mean) * rstd * wv.w + bv.w;
    const size_t base = (size_t)row * D_;
    split_store4(o, g_nh, g_nl, base + (size_t)tid * 4);

    // fused beta: partial dot of normed row with Wb[:,0..3]
    float a0, a1, a2, a3;
    {
        const float4 w0 = ((const float4*)Wb)[tid * 4 + 0];
        const float4 w1 = ((const float4*)Wb)[tid * 4 + 1];
        const float4 w2 = ((const float4*)Wb)[tid * 4 + 2];
        const float4 w3 = ((const float4*)Wb)[tid * 4 + 3];
        a0 = o.x * w0.x + o.y * w1.x + o.z * w2.x + o.w * w3.x;
        a1 = o.x * w0.y + o.y * w1.y + o.z * w2.y + o.w * w3.y;
        a2 = o.x * w0.z + o.y * w1.z + o.z * w2.z + o.w * w3.z;
        a3 = o.x * w0.w + o.y * w1.w + o.z * w2.w + o.w * w3.w;
    }
    #pragma unroll
    for (int off = 16; off > 0; off >>= 1) {
        a0 += __shfl_xor_sync(0xffffffffu, a0, off);
        a1 += __shfl_xor_sync(0xffffffffu, a1, off);
        a2 += __shfl_xor_sync(0xffffffffu, a2, off);
        a3 += __shfl_xor_sync(0xffffffffu, a3, off);
    }
    if (lane == 0) {
        bsh[wid * 4 + 0] = a0; bsh[wid * 4 + 1] = a1;
        bsh[wid * 4 + 2] = a2; bsh[wid * 4 + 3] = a3;
    }
    __syncthreads();
    if (tid == 0) {
        float t0 = 0, t1 = 0, t2 = 0, t3 = 0;
        #pragma unroll
        for (int wq = 0; wq < 8; ++wq) {
            t0 += bsh[wq * 4 + 0]; t1 += bsh[wq * 4 + 1];
            t2 += bsh[wq * 4 + 2]; t3 += bsh[wq * 4 + 3];
        }
        *(float4*)&g_beta[(size_t)row * 4] =
            make_float4(sigmoidf_(t0), sigmoidf_(t1), sigmoidf_(t2), sigmoidf_(t3));
    }
}

// ---------------------------------------------------------------------------
// 1b) weight transpose + bf16 split
// ---------------------------------------------------------------------------
__global__ void __launch_bounds__(256) wtrans_kernel(const float* __restrict__ W,
                                                     __nv_bfloat16* __restrict__ Th,
                                                     __nv_bfloat16* __restrict__ Tl,
                                                     int K, int N) {
    __shared__ float tile[32][33];
    const int tx = threadIdx.x & 31, ty = threadIdx.x >> 5;
    const int k0 = blockIdx.y * 32, n0 = blockIdx.x * 32;
    #pragma unroll
    for (int i = 0; i < 32; i += 8)
        tile[ty + i][tx] = W[(size_t)(k0 + ty + i) * N + n0 + tx];
    __syncthreads();
    #pragma unroll
    for (int i = 0; i < 32; i += 8) {
        const float v = tile[tx][ty + i];
        const size_t oi = (size_t)(n0 + ty + i) * K + k0 + tx;
        const __nv_bfloat16 h = __float2bfloat16(v);
        Th[oi] = h;
        Tl[oi] = __float2bfloat16(v - __bfloat162float(h));
    }
}

// ---------------------------------------------------------------------------
// 2) HMMA GEMM (unchanged, proven)
// ---------------------------------------------------------------------------
#define MG_STAGE 65536
#define MG_SMEM  (2 * MG_STAGE)

__global__ void __launch_bounds__(256, 1)
mma_gemm(const __nv_bfloat16* __restrict__ Ah, const __nv_bfloat16* __restrict__ Al,
         const __nv_bfloat16* __restrict__ Bh, const __nv_bfloat16* __restrict__ Bl,
         float* __restrict__ C, const float* __restrict__ resid,
         int N, int K, int do_silu) {
    extern __shared__ char smx[];
    const uint32_t sbase = smem_u32(smx);
    const int tid = threadIdx.x;
    const int lane = tid & 31;
    const int wid = tid >> 5;
    const int wm = wid >> 2;
    const int wn = wid & 3;
    const int m0w = wm * 64, n0w = wn * 32;

    const size_t bm = (size_t)blockIdx.y * 128;
    const size_t bn = (size_t)blockIdx.x * 128;
    const __nv_bfloat16* pAh = Ah + bm * K;
    const __nv_bfloat16* pAl = Al + bm * K;
    const __nv_bfloat16* pBh = Bh + bn * K;
    const __nv_bfloat16* pBl = Bl + bn * K;

    {
        char* stg = smx;
        #pragma unroll
        for (int p = 0; p < 4; ++p) {
            const int c = tid + (p << 8);
            const int row = c >> 3, ch = c & 7;
            const size_t gi = (size_t)row * K + (ch << 3);
            const int off = (row << 7) + (((ch ^ (row & 7))) << 4);
            *(uint4*)(stg + off)         = *(const uint4*)(pAh + gi);
            *(uint4*)(stg + 16384 + off) = *(const uint4*)(pAl + gi);
            *(uint4*)(stg + 32768 + off) = *(const uint4*)(pBh + gi);
            *(uint4*)(stg + 49152 + off) = *(const uint4*)(pBl + gi);
        }
    }
    __syncthreads();

    float acc[4][4][4];
    #pragma unroll
    for (int i = 0; i < 4; ++i)
        #pragma unroll
        for (int j = 0; j < 4; ++j)
            #pragma unroll
            for (int q = 0; q < 4; ++q) acc[i][j][q] = 0.f;

    const int a_row = m0w + (lane & 15);
    const int a_chs = lane >> 4;
    const int b_row = n0w + ((lane >> 3) & 2) * 4 + (lane & 7);
    const int b_chs = (lane >> 3) & 1;

    const int KB = K >> 6;
    for (int kb = 0; kb < KB; ++kb) {
        const uint32_t stg = sbase + (uint32_t)(kb & 1) * MG_STAGE;
        const bool hasNext = (kb + 1) < KB;

        uint4 vAh[4], vAl[4], vBh[4], vBl[4];
        if (hasNext) {
            const int k0 = (kb + 1) << 6;
            #pragma unroll
            for (int p = 0; p < 4; ++p) {
                const int c = tid + (p << 8);
                const int row = c >> 3, ch = c & 7;
                const size_t gi = (size_t)row * K + k0 + (ch << 3);
                vAh[p] = *(const uint4*)(pAh + gi);
                vAl[p] = *(const uint4*)(pAl + gi);
                vBh[p] = *(const uint4*)(pBh + gi);
                vBl[p] = *(const uint4*)(pBl + gi);
            }
        }

        #pragma unroll
        for (int ks = 0; ks < 4; ++ks) {
            uint32_t afh[4][4], afl[4][4];
            #pragma unroll
            for (int mt = 0; mt < 4; ++mt) {
                const int row = a_row + mt * 16;
                const int ch  = ks * 2 + a_chs;
                const uint32_t off = (uint32_t)((row << 7) + ((ch ^ (row & 7)) << 4));
                ldsm4(afh[mt], stg + off);
                ldsm4(afl[mt], stg + 16384u + off);
            }
            uint32_t bfh[2][4], bfl[2][4];
            #pragma unroll
            for (int np = 0; np < 2; ++np) {
                const int row = b_row + np * 16;
                const int ch  = ks * 2 + b_chs;
                const uint32_t off = (uint32_t)((row << 7) + ((ch ^ (row & 7)) << 4));
                ldsm4(bfh[np], stg + 32768u + off);
                ldsm4(bfl[np], stg + 49152u + off);
            }
            #pragma unroll
            for (int mt = 0; mt < 4; ++mt) {
                #pragma unroll
                for (int nt = 0; nt < 4; ++nt) {
                    const uint32_t* bh = &bfh[nt >> 1][(nt & 1) * 2];
                    const uint32_t* bl = &bfl[nt >> 1][(nt & 1) * 2];
                    mma16816(acc[mt][nt], afh[mt], bh);
                    mma16816(acc[mt][nt], afh[mt], bl);
                    mma16816(acc[mt][nt], afl[mt], bh);
                }
            }
        }

        if (hasNext) {
            char* nst = smx + ((kb + 1) & 1) * MG_STAGE;
            #pragma unroll
            for (int p = 0; p < 4; ++p) {
                const int c = tid + (p << 8);
                const int row = c >> 3, ch = c & 7;
                const int off = (row << 7) + ((ch ^ (row & 7)) << 4);
                *(uint4*)(nst + off)         = vAh[p];
                *(uint4*)(nst + 16384 + off) = vAl[p];
                *(uint4*)(nst + 32768 + off) = vBh[p];
                *(uint4*)(nst + 49152 + off) = vBl[p];
            }
        }
        __syncthreads();
    }

    const int erow = lane >> 2;
    const int ecol = (lane & 3) * 2;
    #pragma unroll
    for (int mt = 0; mt < 4; ++mt) {
        #pragma unroll
        for (int nt = 0; nt < 4; ++nt) {
            const size_t gr0 = bm + m0w + mt * 16 + erow;
            const size_t gc  = bn + n0w + nt * 8 + ecol;
            float v0 = acc[mt][nt][0], v1 = acc[mt][nt][1];
            float v2 = acc[mt][nt][2], v3 = acc[mt][nt][3];
            if (do_silu) { v0 = siluf_(v0); v1 = siluf_(v1); v2 = siluf_(v2); v3 = siluf_(v3); }
            if (resid != nullptr) {
                const float2 r0 = *(const float2*)&resid[gr0 * N + gc];
                const float2 r1 = *(const float2*)&resid[(gr0 + 8) * N + gc];
                v0 += r0.x; v1 += r0.y; v2 += r1.x; v3 += r1.y;
            }
            float2 w0; w0.x = v0; w0.y = v1;
            float2 w1; w1.x = v2; w1.y = v3;
            *(float2*)&C[gr0 * N + gc]       = w0;
            *(float2*)&C[(gr0 + 8) * N + gc] = w1;
        }
    }
}

// ---------------------------------------------------------------------------
// 5a) prep1 (now also does l2norm of k and q, q additionally * DK^-0.5)
// ---------------------------------------------------------------------------
#define P1_FLOATS (17408 + 17408 + 4352 + 64 + 64 + 272)
#define P1_BYTES  (P1_FLOATS * 4)

__global__ void __launch_bounds__(256, 1) prep1_kernel() {
    extern __shared__ float sm1[];
    float* Kt  = sm1;            // [256][68]
    float* wb  = sm1 + 17408;    // [64][260]
    float* Qts = sm1 + 17408;    // [256][68]  (aliases wb)
    float* Ms  = sm1 + 34816;    // [64][68]
    float* bsm = sm1 + 39168;    // [64]
    float* rsk = sm1 + 39232;    // [64]
    float* nrm = sm1 + 39296;    // [4][68]

    const int tid  = threadIdx.x;
    const int cIdx = blockIdx.x;
    const int n = cIdx & 31, h = (cIdx >> 5) & 3, b = cIdx >> 7;
    const size_t m0 = (size_t)b * T_ + n * C_;
    const int hK = h * DK_;

    if (tid < 64) bsm[tid] = g_beta[(m0 + tid) * H_ + h];

    // load K chunk raw (transposed into Kt)
    #pragma unroll 4
    for (int p = 0; p < 16; ++p) {
        const int idx = tid + p * 256;
        const int i = idx >> 6, c4 = idx & 63;
        const float4 v = *(const float4*)&g_k[(m0 + i) * NKV + hK + c4 * 4];
        Kt[(c4 * 4 + 0) * 68 + i] = v.x;
        Kt[(c4 * 4 + 1) * 68 + i] = v.y;
        Kt[(c4 * 4 + 2) * 68 + i] = v.z;
        Kt[(c4 * 4 + 3) * 68 + i] = v.w;
    }
    __syncthreads();

    // l2norm of k: per-column sumsq
    {
        const int i = tid & 63, part = tid >> 6;
        float ss = 0.f;
        #pragma unroll 4
        for (int kk = part * 64; kk < part * 64 + 64; ++kk) {
            const float vv = Kt[kk * 68 + i];
            ss += vv * vv;
        }
        nrm[part * 68 + i] = ss;
    }
    __syncthreads();
    if (tid < 64)
        rsk[tid] = rsqrtf(nrm[tid] + nrm[68 + tid] + nrm[136 + tid] + nrm[204 + tid] + 1e-6f);
    __syncthreads();
    // scale Kt in place
    for (int idx = tid; idx < 4352; idx += 256) {
        const int kk = idx / 17, f4 = idx % 17;
        if (f4 < 16) {
            float4 v = *(float4*)&Kt[kk * 68 + f4 * 4];
            const float4 r = *(const float4*)&rsk[f4 * 4];
            v.x *= r.x; v.y *= r.y; v.z *= r.z; v.w *= r.w;
            *(float4*)&Kt[kk * 68 + f4 * 4] = v;
        }
    }
    __syncthreads();

    const int ty = tid >> 4, tx = tid & 15;
    const int ti4 = ty * 4, tj4 = tx * 4;

    // wb = beta_i * k_i (rows) from scaled Kt
    #pragma unroll 4
    for (int p = 0; p < 16; ++p) {
        const int idx = tid + p * 256;
        const int i = idx >> 6, c4 = idx & 63;
        const float bb = bsm[i];
        float4 v;
        v.x = bb * Kt[(c4 * 4 + 0) * 68 + i];
        v.y = bb * Kt[(c4 * 4 + 1) * 68 + i];
        v.z = bb * Kt[(c4 * 4 + 2) * 68 + i];
        v.w = bb * Kt[(c4 * 4 + 3) * 68 + i];
        *(float4*)&wb[i * 260 + c4 * 4] = v;
    }

    // M = beta_i * strict_tril(K K^T) from scaled Kt
    {
        ull acc[4][2] = {};
        #pragma unroll 4
        for (int kk = 0; kk < 256; ++kk) {
            const float4 a4 = *(const float4*)&Kt[kk * 68 + ti4];
            const float4 b4 = *(const float4*)&Kt[kk * 68 + tj4];
            mma4x4p(acc, a4, pack2(b4.x, b4.y), pack2(b4.z, b4.w));
        }
        float mo[4][4]; unp4x4(acc, mo);
        #pragma unroll
        for (int r = 0; r < 4; ++r) {
            const int i = ti4 + r;
            const float bi = bsm[i];
            #pragma unroll
            for (int cc = 0; cc < 4; ++cc) {
                const int j = tj4 + cc;
                Ms[i * 68 + j] = (j < i) ? bi * mo[r][cc] : 0.f;
            }
        }
    }

    // Kt split store (scaled)
    {
        __nv_bfloat16* kth = g_cKth + (size_t)cIdx * 16384;
        __nv_bfloat16* ktl = g_cKtl + (size_t)cIdx * 16384;
        for (int idx = tid; idx < 8192; idx += 256) {
            const int kk = idx >> 5, i2 = (idx & 31) * 2;
            uint32_t hi, lo;
            split2(Kt[kk * 68 + i2], Kt[kk * 68 + i2 + 1], hi, lo);
            *(uint32_t*)(kth + kk * 64 + i2) = hi;
            *(uint32_t*)(ktl + kk * 64 + i2) = lo;
        }
    }
    __syncthreads();

    // forward substitution: W_i = beta_i k_i - sum_{j<i} M[i][j] W_j
    for (int i = 1; i < 64; ++i) {
        const float* mr = Ms + i * 68;
        float a0 = 0.f, a1 = 0.f, a2 = 0.f, a3 = 0.f;
        int j = 0;
        for (; j + 4 <= i; j += 4) {
            a0 += mr[j + 0] * wb[(j + 0) * 260 + tid];
            a1 += mr[j + 1] * wb[(j + 1) * 260 + tid];
            a2 += mr[j + 2] * wb[(j + 2) * 260 + tid];
            a3 += mr[j + 3] * wb[(j + 3) * 260 + tid];
        }
        for (; j < i; ++j) a0 += mr[j] * wb[j * 260 + tid];
        wb[i * 260 + tid] -= (a0 + a1) + (a2 + a3);
        __syncthreads();
    }

    // store W split [i][kk] + M fp32
    {
        __nv_bfloat16* wh = g_cWh + (size_t)cIdx * 16384;
        __nv_bfloat16* wl = g_cWl + (size_t)cIdx * 16384;
        for (int idx = tid; idx < 8192; idx += 256) {
            const int i = idx >> 7, kk2 = (idx & 127) * 2;
            uint32_t hi, lo;
            split2(wb[i * 260 + kk2], wb[i * 260 + kk2 + 1], hi, lo);
            *(uint32_t*)(wh + i * 256 + kk2) = hi;
            *(uint32_t*)(wl + i * 256 + kk2) = lo;
        }
        float* mo = g_mlt + (size_t)cIdx * (C_ * C_);
        for (int idx = tid; idx < C_ * C_; idx += 256)
            mo[idx] = Ms[(idx >> 6) * 68 + (idx & 63)];
    }
    __syncthreads();   // wb dead; Qts may now overwrite

    // load Q chunk raw (transposed into Qts)
    #pragma unroll 4
    for (int p = 0; p < 16; ++p) {
        const int idx = tid + p * 256;
        const int i = idx >> 6, c4 = idx & 63;
        const float4 v = *(const float4*)&g_q[(m0 + i) * NKV + hK + c4 * 4];
        Qts[(c4 * 4 + 0) * 68 + i] = v.x;
        Qts[(c4 * 4 + 1) * 68 + i] = v.y;
        Qts[(c4 * 4 + 2) * 68 + i] = v.z;
        Qts[(c4 * 4 + 3) * 68 + i] = v.w;
    }
    __syncthreads();

    // l2norm of q (with * DK^-0.5)
    {
        const int i = tid & 63, part = tid >> 6;
        float ss = 0.f;
        #pragma unroll 4
        for (int kk = part * 64; kk < part * 64 + 64; ++kk) {
            const float vv = Qts[kk * 68 + i];
            ss += vv * vv;
        }
        nrm[part * 68 + i] = ss;
    }
    __syncthreads();
    if (tid < 64)
        rsk[tid] = rsqrtf(nrm[tid] + nrm[68 + tid] + nrm[136 + tid] + nrm[204 + tid] + 1e-6f) * 0.0625f;
    __syncthreads();
    for (int idx = tid; idx < 4352; idx += 256) {
        const int kk = idx / 17, f4 = idx % 17;
        if (f4 < 16) {
            float4 v = *(float4*)&Qts[kk * 68 + f4 * 4];
            const float4 r = *(const float4*)&rsk[f4 * 4];
            v.x *= r.x; v.y *= r.y; v.z *= r.z; v.w *= r.w;
            *(float4*)&Qts[kk * 68 + f4 * 4] = v;
        }
    }
    __syncthreads();

    // Q split store [i][kk] from scaled Qts
    {
        __nv_bfloat16* qh = g_cQh + (size_t)cIdx * 16384;
        __nv_bfloat16* ql = g_cQl + (size_t)cIdx * 16384;
        for (int idx = tid; idx < 8192; idx += 256) {
            const int i = idx >> 7, kk2 = (idx & 127) * 2;
            uint32_t hi, lo;
            split2(Qts[kk2 * 68 + i], Qts[(kk2 + 1) * 68 + i], hi, lo);
            *(uint32_t*)(qh + i * 256 + kk2) = hi;
            *(uint32_t*)(ql + i * 256 + kk2) = lo;
        }
    }

    // P = tril_incl(Q K^T) -> split bf16 [i][j]
    {
        ull acc[4][2] = {};
        #pragma unroll 4
        for (int kk = 0; kk < 256; ++kk) {
            const float4 a4 = *(const float4*)&Qts[kk * 68 + ti4];
            const float4 b4 = *(const float4*)&Kt[kk * 68 + tj4];
            mma4x4p(acc, a4, pack2(b4.x, b4.y), pack2(b4.z, b4.w));
        }
        float po[4][4]; unp4x4(acc, po);
        __nv_bfloat16* ph = g_cPh + (size_t)cIdx * 4096;
        __nv_bfloat16* pl = g_cPl + (size_t)cIdx * 4096;
        #pragma unroll
        for (int r = 0; r < 4; ++r) {
            const int i = ti4 + r;
            const float v0 = (tj4 + 0 <= i) ? po[r][0] : 0.f;
            const float v1 = (tj4 + 1 <= i) ? po[r][1] : 0.f;
            const float v2 = (tj4 + 2 <= i) ? po[r][2] : 0.f;
            const float v3 = (tj4 + 3 <= i) ? po[r][3] : 0.f;
            uint32_t hi, lo;
            split2(v0, v1, hi, lo);
            *(uint32_t*)(ph + i * 64 + tj4)     = hi;
            *(uint32_t*)(pl + i * 64 + tj4)     = lo;
            split2(v2, v3, hi, lo);
            *(uint32_t*)(ph + i * 64 + tj4 + 2) = hi;
            *(uint32_t*)(pl + i * 64 + tj4 + 2) = lo;
        }
    }
}

// ---------------------------------------------------------------------------
// 5b) prep2: Uv = (I+M)^{-1} (beta V)  -> g_Uv (unchanged)
// ---------------------------------------------------------------------------
#define P2_FLOATS (33280 + 4352 + 64)
#define P2_BYTES  (P2_FLOATS * 4)

__global__ void __launch_bounds__(256, 1) prep2_kernel() {
    extern __shared__ float sm2[];
    float* vb  = sm2;            // [64][520]
    float* Ms  = sm2 + 33280;    // [64][68]
    float* bsm = sm2 + 33280 + 4352;

    const int tid  = threadIdx.x;
    const int cIdx = blockIdx.x;
    const int n = cIdx & 31, h = (cIdx >> 5) & 3, b = cIdx >> 7;
    const size_t m0 = (size_t)b * T_ + n * C_;
    const int hV = h * DV_;

    if (tid < 64) bsm[tid] = g_beta[(m0 + tid) * H_ + h];
    {
        const float* mg = g_mlt + (size_t)cIdx * (C_ * C_);
        for (int idx = tid; idx < C_ * C_; idx += 256)
            Ms[(idx >> 6) * 68 + (idx & 63)] = mg[idx];
    }
    __syncthreads();

    #pragma unroll 4
    for (int p = 0; p < 32; ++p) {
        const int idx = tid + p * 256;
        const int i = idx >> 7, c4 = idx & 127;
        float4 v = *(const float4*)&g_v[(m0 + i) * NV + hV + c4 * 4];
        const float bb = bsm[i];
        v.x *= bb; v.y *= bb; v.z *= bb; v.w *= bb;
        *(float4*)&vb[i * 520 + c4 * 4] = v;
    }
    __syncthreads();

    const int col2 = 2 * tid;
    for (int i = 1; i < 64; ++i) {
        const float* mr = Ms + i * 68;
        ull acc = 0ull;
        for (int j = 0; j < i; ++j) {
            const float m = mr[j];
            const ull v = *(const ull*)&vb[j * 520 + col2];
            ffma2(acc, pack2(m, m), v);
        }
        float ax, ay; unpack2(acc, ax, ay);
        vb[i * 520 + col2]     -= ax;
        vb[i * 520 + col2 + 1] -= ay;
        __syncthreads();
    }

    float* uo = g_Uv + (size_t)cIdx * (C_ * DV_);
    #pragma unroll 4
    for (int p = 0; p < 32; ++p) {
        const int idx = tid + p * 256;
        const int i = idx >> 7, c4 = idx & 127;
        *(float4*)&uo[i * DV_ + c4 * 4] = *(const float4*)&vb[i * 520 + c4 * 4];
    }
}

// ---------------------------------------------------------------------------
// 5c) chunkscan v3 (HMMA, 512 threads / 16 warps, warp grid 4x4)
//     Per chunk: U = Uv - W·S ; O = Q·S + P·U ; S += K^T·U
// ---------------------------------------------------------------------------
#define CST 512
#define CS2_SH   69632
#define CS2_SL   102400
#define CS2_UH   135168
#define CS2_UL   143360
#define CS2_UVS  151552
#define CS2_STG  168960
#define CS2_BYTES 201728

__global__ void __launch_bounds__(CST, 1) chunkscan_kernel() {
    extern __shared__ char sm3[];
    float* SF  = (float*)sm3;                 // [256][68] fp32
    char*  SH  = sm3 + CS2_SH;                // [256][64] bf16 swizzled
    char*  SL  = sm3 + CS2_SL;
    char*  UH  = sm3 + CS2_UH;                // [64][64] bf16 swizzled
    char*  UL  = sm3 + CS2_UL;
    float* UVS = (float*)(sm3 + CS2_UVS);     // [64][68] fp32
    char*  STG = sm3 + CS2_STG;               // 4 x 8192B tiles

    const uint32_t stg_u = smem_u32(STG);
    const uint32_t sh_u  = smem_u32(SH);
    const uint32_t sl_u  = smem_u32(SL);
    const uint32_t uh_u  = smem_u32(UH);
    const uint32_t ul_u  = smem_u32(UL);

    const int tid  = threadIdx.x;
    const int lane = tid & 31, wid = tid >> 5;      // 16 warps
    const int wm = wid >> 2, wn = wid & 3;          // 4 x 4
    const int erow = lane >> 2, ecol = (lane & 3) * 2;
    const int lrow = lane & 15, lhi = lane >> 4;
    const int c = blockIdx.x & 7, h = (blockIdx.x >> 3) & 3, b = blockIdx.x >> 5;
    const int dv0 = c * 64;
    const int srow = tid >> 3, sch = tid & 7;       // staging role (512 = 64 rows x 8 ch)
    const uint32_t sso = swz(srow, sch);

    for (int i = tid; i < 17408; i += CST) SF[i] = 0.f;
    for (int i = tid; i < 8192; i += CST) { ((uint32_t*)SH)[i] = 0u; ((uint32_t*)SL)[i] = 0u; }
    __syncthreads();

    for (int n = 0; n < NC_; ++n) {
        const int cIdx = b * 128 + h * 32 + n;
        const __nv_bfloat16* Wh  = g_cWh  + (size_t)cIdx * 16384;
        const __nv_bfloat16* Wl  = g_cWl  + (size_t)cIdx * 16384;
        const __nv_bfloat16* Qh  = g_cQh  + (size_t)cIdx * 16384;
        const __nv_bfloat16* Ql  = g_cQl  + (size_t)cIdx * 16384;
        const __nv_bfloat16* Kth = g_cKth + (size_t)cIdx * 16384;
        const __nv_bfloat16* Ktl = g_cKtl + (size_t)cIdx * 16384;
        const __nv_bfloat16* Ph  = g_cPh  + (size_t)cIdx * 4096;
        const __nv_bfloat16* Pl  = g_cPl  + (size_t)cIdx * 4096;
        const float* Uvg = g_Uv + (size_t)cIdx * 32768 + dv0;
        const size_t m0  = (size_t)b * T_ + n * 64;

        // stage W/Q block 0 + Uv
        {
            const size_t gi = (size_t)srow * 256 + sch * 8;
            *(uint4*)(STG + sso)         = *(const uint4*)(Wh + gi);
            *(uint4*)(STG + 8192 + sso)  = *(const uint4*)(Wl + gi);
            *(uint4*)(STG + 16384 + sso) = *(const uint4*)(Qh + gi);
            *(uint4*)(STG + 24576 + sso) = *(const uint4*)(Ql + gi);
        }
        #pragma unroll
        for (int j = 0; j < 2; ++j) {
            const int idx = tid + j * CST;
            const int r = idx >> 4, c4 = idx & 15;
            *(float4*)&UVS[r * 68 + c4 * 4] = *(const float4*)&Uvg[(size_t)r * DV_ + c4 * 4];
        }
        __syncthreads();

        float accU[2][4] = {}, accO[2][4] = {};

        // GEMM1+2a: accU = W·S, accO = Q·S over 4 kk-blocks
        for (int kb = 0; kb < 4; ++kb) {
            uint4 pf[4];
            if (kb < 3) {
                const size_t gi = (size_t)srow * 256 + (kb + 1) * 64 + sch * 8;
                pf[0] = *(const uint4*)(Wh + gi);
                pf[1] = *(const uint4*)(Wl + gi);
                pf[2] = *(const uint4*)(Qh + gi);
                pf[3] = *(const uint4*)(Ql + gi);
            }
            #pragma unroll
            for (int ks = 0; ks < 4; ++ks) {
                uint32_t wfh[4], wfl[4], qfh[4], qfl[4];
                const int ar = wm * 16 + lrow;
                const uint32_t ao = swz(ar, ks * 2 + lhi);
                ldsm4(wfh, stg_u + ao);
                ldsm4(wfl, stg_u + 8192u + ao);
                ldsm4(qfh, stg_u + 16384u + ao);
                ldsm4(qfl, stg_u + 24576u + ao);
                uint32_t sfh[4], sfl[4];
                const int br = kb * 64 + ks * 16 + lrow;
                const uint32_t bo = swz(br, wn * 2 + lhi);
                ldsm4t(sfh, sh_u + bo);
                ldsm4t(sfl, sl_u + bo);
                #pragma unroll
                for (int nt = 0; nt < 2; ++nt) {
                    mma16816(accU[nt], wfh, sfh + nt * 2);
                    mma16816(accU[nt], wfh, sfl + nt * 2);
                    mma16816(accU[nt], wfl, sfh + nt * 2);
                    mma16816(accO[nt], qfh, sfh + nt * 2);
                    mma16816(accO[nt], qfh, sfl + nt * 2);
                    mma16816(accO[nt], qfl, sfh + nt * 2);
                }
            }
            __syncthreads();
            if (kb < 3) {
                *(uint4*)(STG + sso)         = pf[0];
                *(uint4*)(STG + 8192 + sso)  = pf[1];
                *(uint4*)(STG + 16384 + sso) = pf[2];
                *(uint4*)(STG + 24576 + sso) = pf[3];
                __syncthreads();
            }
        }

        // U finalize (u = Uv - accU) -> UH/UL
        #pragma unroll
        for (int nt = 0; nt < 2; ++nt) {
            const int r0 = wm * 16 + erow;
            const int cc = wn * 16 + nt * 8 + ecol;
            const float u0 = UVS[r0 * 68 + cc]           - accU[nt][0];
            const float u1 = UVS[r0 * 68 + cc + 1]       - accU[nt][1];
            const float u2 = UVS[(r0 + 8) * 68 + cc]     - accU[nt][2];
            const float u3 = UVS[(r0 + 8) * 68 + cc + 1] - accU[nt][3];
            uint32_t hi, lo;
            split2(u0, u1, hi, lo);
            *(uint32_t*)(UH + swzb(r0, cc)) = hi;
            *(uint32_t*)(UL + swzb(r0, cc)) = lo;
            split2(u2, u3, hi, lo);
            *(uint32_t*)(UH + swzb(r0 + 8, cc)) = hi;
            *(uint32_t*)(UL + swzb(r0 + 8, cc)) = lo;
        }
        // stage P -> T0/T1, Kt block0 -> T2/T3
        {
            const size_t gp = (size_t)srow * 64 + sch * 8;
            *(uint4*)(STG + sso)         = *(const uint4*)(Ph + gp);
            *(uint4*)(STG + 8192 + sso)  = *(const uint4*)(Pl + gp);
            *(uint4*)(STG + 16384 + sso) = *(const uint4*)(Kth + gp);
            *(uint4*)(STG + 24576 + sso) = *(const uint4*)(Ktl + gp);
        }
        __syncthreads();

        // hoist U B-fragments for all 4 k-steps (shared by GEMM2b and GEMM3)
        uint32_t ufh[4][4], ufl[4][4];
        #pragma unroll
        for (int ks = 0; ks < 4; ++ks) {
            const int br = ks * 16 + lrow;
            const uint32_t bo = swz(br, wn * 2 + lhi);
            ldsm4t(ufh[ks], uh_u + bo);
            ldsm4t(ufl[ks], ul_u + bo);
        }

        // GEMM2b: accO += P·U
        #pragma unroll
        for (int ks = 0; ks < 4; ++ks) {
            uint32_t pfh[4], pfl[4];
            const int ar = wm * 16 + lrow;
            const uint32_t ao = swz(ar, ks * 2 + lhi);
            ldsm4(pfh, stg_u + ao);
            ldsm4(pfl, stg_u + 8192u + ao);
            #pragma unroll
            for (int nt = 0; nt < 2; ++nt) {
                mma16816(accO[nt], pfh, ufh[ks] + nt * 2);
                mma16816(accO[nt], pfh, ufl[ks] + nt * 2);
                mma16816(accO[nt], pfl, ufh[ks] + nt * 2);
            }
        }

        // O epilogue -> global
        #pragma unroll
        for (int nt = 0; nt < 2; ++nt) {
            const int r0 = wm * 16 + erow;
            const int cc = wn * 16 + nt * 8 + ecol;
            float2 w0; w0.x = accO[nt][0]; w0.y = accO[nt][1];
            float2 w1; w1.x = accO[nt][2]; w1.y = accO[nt][3];
            *(float2*)&g_o[(m0 + r0) * NV + h * DV_ + dv0 + cc]     = w0;
            *(float2*)&g_o[(m0 + r0 + 8) * NV + h * DV_ + dv0 + cc] = w1;
        }
        __syncthreads();   // retire P reads (T0/T1) before GEMM3 stores there

        // GEMM3: S += K^T · U, 4 kk-blocks, double-buffered halves
        for (int kkb = 0; kkb < 4; ++kkb) {
            float accS[2][4] = {};
            uint4 kf[2];
            if (kkb < 3) {
                const size_t gi = (size_t)((kkb + 1) * 64 + srow) * 64 + sch * 8;
                kf[0] = *(const uint4*)(Kth + gi);
                kf[1] = *(const uint4*)(Ktl + gi);
            }
            const uint32_t curH = stg_u + ((kkb & 1) ? 0u : 16384u);
            const uint32_t curL = stg_u + ((kkb & 1) ? 8192u : 24576u);
            #pragma unroll
            for (int ks = 0; ks < 4; ++ks) {
                uint32_t kfh[4], kfl[4];
                const int ar = wm * 16 + lrow;
                const uint32_t ao = swz(ar, ks * 2 + lhi);
                ldsm4(kfh, curH + ao);
                ldsm4(kfl, curL + ao);
                #pragma unroll
                for (int nt = 0; nt < 2; ++nt) {
                    mma16816(accS[nt], kfh, ufh[ks] + nt * 2);
                    mma16816(accS[nt], kfh, ufl[ks] + nt * 2);
                    mma16816(accS[nt], kfl, ufh[ks] + nt * 2);
                }
            }
            // S finalize: fp32 RMW + bf16 re-split for this 64-row block
            #pragma unroll
            for (int nt = 0; nt < 2; ++nt) {
                const int sr = kkb * 64 + wm * 16 + erow;
                const int sc = wn * 16 + nt * 8 + ecol;
                const float s0 = SF[sr * 68 + sc]           + accS[nt][0];
                const float s1 = SF[sr * 68 + sc + 1]       + accS[nt][1];
                const float s2 = SF[(sr + 8) * 68 + sc]     + accS[nt][2];
                const float s3 = SF[(sr + 8) * 68 + sc + 1] + accS[nt][3];
                SF[sr * 68 + sc]           = s0;
                SF[sr * 68 + sc + 1]       = s1;
                SF[(sr + 8) * 68 + sc]     = s2;
                SF[(sr + 8) * 68 + sc + 1] = s3;
                uint32_t hi, lo;
                split2(s0, s1, hi, lo);
                *(uint32_t*)(SH + swzb(sr, sc)) = hi;
                *(uint32_t*)(SL + swzb(sr, sc)) = lo;
                split2(s2, s3, hi, lo);
                *(uint32_t*)(SH + swzb(sr + 8, sc)) = hi;
                *(uint32_t*)(SL + swzb(sr + 8, sc)) = lo;
            }
            __syncthreads();
            if (kkb < 3) {
                char* oH = STG + ((kkb & 1) ? 16384 : 0);
                char* oL = STG + ((kkb & 1) ? 24576 : 8192);
                *(uint4*)(oH + sso) = kf[0];
                *(uint4*)(oL + sso) = kf[1];
                __syncthreads();
            }
        }
    }
}

// ---------------------------------------------------------------------------
// 6) per-head RMSNorm on g_o -> bf16 split g_oh/g_ol
// ---------------------------------------------------------------------------
__global__ void __launch_bounds__(256) rmsnorm_kernel(const float* __restrict__ w) {
    const int grp  = blockIdx.x * 8 + (threadIdx.x >> 5);
    const int lane = threadIdx.x & 31;
    const float* base = g_o + (size_t)grp * DV_;
    float4 v[4];
    float ss = 0.f;
    #pragma unroll
    for (int i = 0; i < 4; ++i) {
        v[i] = ((const float4*)base)[lane + 32 * i];
        ss += v[i].x * v[i].x + v[i].y * v[i].y + v[i].z * v[i].z + v[i].w * v[i].w;
    }
    #pragma unroll
    for (int off = 16; off > 0; off >>= 1) ss += __shfl_xor_sync(0xffffffffu, ss, off);
    const float rs = rsqrtf(ss * (1.0f / DV_) + 1e-5f);
    #pragma unroll
    for (int i = 0; i < 4; ++i) {
        const int idx = lane + 32 * i;
        const float4 wv = ((const float4*)w)[idx];
        const float4 o = make_float4(v[i].x * rs * wv.x, v[i].y * rs * wv.y,
                                     v[i].z * rs * wv.z, v[i].w * rs * wv.w);
        split_store4(o, g_oh, g_ol, (size_t)grp * DV_ + (size_t)idx * 4);
    }
}

// ---------------------------------------------------------------------------
// Launch
// ---------------------------------------------------------------------------
extern "C" void kernel_launch(void* const* d_in, const int* in_sizes, int n_in,
                              void* d_out, int out_size) {
    const float* x        = (const float*)d_in[0];
    const float* ln_w     = (const float*)d_in[1];
    const float* ln_b     = (const float*)d_in[2];
    const float* Wq       = (const float*)d_in[3];
    const float* Wk       = (const float*)d_in[4];
    const float* Wv       = (const float*)d_in[5];
    const float* Wb       = (const float*)d_in[6];
    const float* o_norm_w = (const float*)d_in[7];
    const float* Wo       = (const float*)d_in[8];
    float* out = (float*)d_out;

    cudaFuncSetAttribute(mma_gemm, cudaFuncAttributeMaxDynamicSharedMemorySize, MG_SMEM);
    cudaFuncSetAttribute(prep1_kernel, cudaFuncAttributeMaxDynamicSharedMemorySize, P1_BYTES);
    cudaFuncSetAttribute(prep2_kernel, cudaFuncAttributeMaxDynamicSharedMemorySize, P2_BYTES);
    cudaFuncSetAttribute(chunkscan_kernel, cudaFuncAttributeMaxDynamicSharedMemorySize, CS2_BYTES);

    __nv_bfloat16 *nh, *nl, *oh, *ol, *wqh, *wql, *wkh, *wkl, *wvh, *wvl, *woh, *wol;
    cudaGetSymbolAddress((void**)&nh,  g_nh);
    cudaGetSymbolAddress((void**)&nl,  g_nl);
    cudaGetSymbolAddress((void**)&oh,  g_oh);
    cudaGetSymbolAddress((void**)&ol,  g_ol);
    cudaGetSymbolAddress((void**)&wqh, g_Wqt_h);
    cudaGetSymbolAddress((void**)&wql, g_Wqt_l);
    cudaGetSymbolAddress((void**)&wkh, g_Wkt_h);
    cudaGetSymbolAddress((void**)&wkl, g_Wkt_l);
    cudaGetSymbolAddress((void**)&wvh, g_Wvt_h);
    cudaGetSymbolAddress((void**)&wvl, g_Wvt_l);
    cudaGetSymbolAddress((void**)&woh, g_Wot_h);
    cudaGetSymbolAddress((void**)&wol, g_Wot_l);
    float *gq, *gk, *gv;
    cudaGetSymbolAddress((void**)&gq, g_q);
    cudaGetSymbolAddress((void**)&gk, g_k);
    cudaGetSymbolAddress((void**)&gv, g_v);

    // 1) LayerNorm (+ bf16 split of normed, + fused beta)
    ln_kernel<<<M_, 256>>>(x, ln_w, ln_b, Wb);

    // 1b) weight transpose+split
    wtrans_kernel<<<dim3(NKV / 32, D_ / 32), 256>>>(Wq, wqh, wql, D_, NKV);
    wtrans_kernel<<<dim3(NKV / 32, D_ / 32), 256>>>(Wk, wkh, wkl, D_, NKV);
    wtrans_kernel<<<dim3(NV  / 32, D_ / 32), 256>>>(Wv, wvh, wvl, D_, NV);
    wtrans_kernel<<<dim3(D_  / 32, NV / 32), 256>>>(Wo, woh, wol, NV, D_);

    // 2) projections (HMMA, silu fused)
    mma_gemm<<<dim3(NKV / 128, M_ / 128), 256, MG_SMEM>>>(nh, nl, wqh, wql, gq, nullptr, NKV, D_, 1);
    mma_gemm<<<dim3(NKV / 128, M_ / 128), 256, MG_SMEM>>>(nh, nl, wkh, wkl, gk, nullptr, NKV, D_, 1);
    mma_gemm<<<dim3(NV  / 128, M_ / 128), 256, MG_SMEM>>>(nh, nl, wvh, wvl, gv, nullptr, NV,  D_, 1);

    // 5) chunked delta-rule (prep1 includes l2norm of q/k)
    prep1_kernel<<<NCH, 256, P1_BYTES>>>();
    prep2_kernel<<<NCH, 256, P2_BYTES>>>();
    chunkscan_kernel<<<B_ * H_ * 8, CST, CS2_BYTES>>>();

    // 6) RMSNorm (+ bf16 split of o)
    rmsnorm_kernel<<<(M_ * H_) / 8, 256>>>(o_norm_w);

    // 7) output projection + residual (HMMA)
    mma_gemm<<<dim3(D_ / 128, M_ / 128), 256, MG_SMEM>>>(oh, ol, woh, wol, out, x, D_, NV, 0);
}